// round 9
// baseline (speedup 1.0000x reference)
#include <cuda_runtime.h>
#include <cuda_bf16.h>
#include <math.h>
#include <stdint.h>

// Problem constants
#define NCTX   4096
#define DMODEL 1024
#define NHEAD  16
#define DHEAD  64
#define DEPTH  4
#define PFX    3072
#define LAT    1024          // NCTX - PFX
#define FFDIM  4096
#define VOCAB  32000
#define INNER  1024          // NHEAD * DHEAD

// ---------------------------------------------------------------------------
// Scratch (static __device__ globals; no runtime allocation)
// ---------------------------------------------------------------------------
__device__ float g_prefix[PFX * DMODEL];
__device__ float g_h     [LAT * DMODEL];
__device__ float g_xn    [LAT * DMODEL];
__device__ float g_q     [LAT * INNER];
__device__ float g_kvin  [LAT * 2 * INNER];
__device__ float g_kvctx [PFX * 2 * INNER];
__device__ float g_attn  [LAT * INNER];
__device__ float g_ff    [LAT * FFDIM];
__device__ float g_qkv   [LAT * 3 * INNER];

// ---------------------------------------------------------------------------
// Embedding
// ---------------------------------------------------------------------------
__global__ void embed_kernel(const int* __restrict__ x,
                             const float* __restrict__ tok,
                             const float* __restrict__ pos)
{
    int idx = blockIdx.x * blockDim.x + threadIdx.x;
    int n = idx >> 10;
    int d = idx & 1023;
    float v = tok[(size_t)x[n] * DMODEL + d] + pos[idx];
    if (n < PFX) g_prefix[(size_t)n * DMODEL + d] = v;
    else         g_h[(size_t)(n - PFX) * DMODEL + d] = v;
}

// ---------------------------------------------------------------------------
// LayerNorm (D=1024), one block per row
// ---------------------------------------------------------------------------
__global__ __launch_bounds__(256) void ln_kernel(
    const float* __restrict__ in, float* __restrict__ out,
    const float* __restrict__ g, const float* __restrict__ b)
{
    int row = blockIdx.x;
    const float* p = in + (size_t)row * DMODEL;
    float vals[4];
    float s = 0.f, s2 = 0.f;
#pragma unroll
    for (int u = 0; u < 4; u++) {
        float v = p[threadIdx.x + u * 256];
        vals[u] = v; s += v; s2 += v * v;
    }
#pragma unroll
    for (int o = 16; o; o >>= 1) {
        s  += __shfl_xor_sync(0xffffffffu, s,  o);
        s2 += __shfl_xor_sync(0xffffffffu, s2, o);
    }
    __shared__ float sh[2][8];
    int wid = threadIdx.x >> 5, lane = threadIdx.x & 31;
    if (lane == 0) { sh[0][wid] = s; sh[1][wid] = s2; }
    __syncthreads();
    s = 0.f; s2 = 0.f;
#pragma unroll
    for (int w = 0; w < 8; w++) { s += sh[0][w]; s2 += sh[1][w]; }
    float mean = s * (1.f / DMODEL);
    float var  = s2 * (1.f / DMODEL) - mean * mean;
    float inv  = rsqrtf(var + 1e-5f);
#pragma unroll
    for (int u = 0; u < 4; u++) {
        int d = threadIdx.x + u * 256;
        out[(size_t)row * DMODEL + d] = (vals[u] - mean) * inv * g[d] + b[d];
    }
}

// ---------------------------------------------------------------------------
// TF32 tensor-core GEMM: C[M,N] = A[M,K] @ B[K,N]  (row-major)
// mma.sync.m16n8k8 tf32, fp32 accumulate.
// Block tile BMx128 (BM = 128 or 64), BK=16, 256 threads = 8 warps (2M x 4N).
// Pair-interleaved smem: within each 16-wide group, logical index r maps to
// slot 2*(r&7) + (r>>3), so fragment rows (m, m+8) / cols (n, n+8) are
// ADJACENT -> fragment loads are LDS.64 (24 per k-tile vs 96 LDS.32).
// Pitches == 8 mod 32 keep loads conflict-free. Smem 16B-aligned for LDS.64.
// Epilogues: 0 none | 1 +bias[col]+res | 2 +res | 3 exact GELU
// ---------------------------------------------------------------------------
#define BK 16

__device__ __forceinline__ uint32_t f2tf(float x) {
    uint32_t r;
    asm("cvt.rna.tf32.f32 %0, %1;" : "=r"(r) : "f"(x));
    return r;
}

__device__ __forceinline__ void mma_tf32(float* d, const uint32_t* a, const uint32_t* b) {
    asm volatile(
        "mma.sync.aligned.m16n8k8.row.col.f32.tf32.tf32.f32 "
        "{%0,%1,%2,%3}, {%4,%5,%6,%7}, {%8,%9}, {%0,%1,%2,%3};"
        : "+f"(d[0]), "+f"(d[1]), "+f"(d[2]), "+f"(d[3])
        : "r"(a[0]), "r"(a[1]), "r"(a[2]), "r"(a[3]), "r"(b[0]), "r"(b[1]));
}

__device__ __forceinline__ int pair_map(int r) {
    // within-16 pair interleave: r -> (r&~15) | ((r&7)<<1) | ((r>>3)&1)
    return (r & ~15) | ((r & 7) << 1) | ((r >> 3) & 1);
}

template <int BM, int EPI>
__global__ __launch_bounds__(256, 2) void sgemm_kernel(
    const float* __restrict__ A, const float* __restrict__ B,
    float* __restrict__ C, const float* __restrict__ bias,
    const float* __restrict__ res, int M, int Nn, int K)
{
    constexpr int MF = BM / 32;       // m-fragments per warp
    constexpr int AP = BM + 8;        // A smem pitch (== 8 mod 32, even)
    constexpr int BP = 136;           // B smem pitch (== 8 mod 32, even)
    __shared__ __align__(16) uint32_t As[2][BK][AP];
    __shared__ __align__(16) uint32_t Bs[2][BK][BP];

    const int tid  = threadIdx.x;
    const int lane = tid & 31, wid = tid >> 5;       // 8 warps
    const int g = lane >> 2, c = lane & 3;
    const int wm = (wid & 1) * (BM / 2);             // warp M offset
    const int wn = (wid >> 1) * 32;                  // warp N offset
    const int bx = blockIdx.x, by = blockIdx.y;

    // Global load mapping
    const int arow  = (BM == 128) ? (tid >> 1) : (tid >> 2);
    const int acol  = (BM == 128) ? ((tid & 1) * 8) : ((tid & 3) * 4);
    const int bkrow = tid >> 5;          // 0..7 (and +8)
    const int bncol = (tid & 31) * 4;    // 0..124

    const int apr = pair_map(arow);          // paired slot for A row
    const int bpr = pair_map(bncol);         // paired slot base for B cols (+2j)

    const float* Ap = A + (size_t)(by * BM + arow) * K + acol;
    const float* Bp = B + (size_t)bkrow * Nn + bx * 128 + bncol;

    float acc[MF][4][4];
#pragma unroll
    for (int mf = 0; mf < MF; mf++)
#pragma unroll
        for (int nf = 0; nf < 4; nf++)
#pragma unroll
            for (int i = 0; i < 4; i++) acc[mf][nf][i] = 0.f;

    const int nt = K / BK;

    float4 pa0, pa1, pb0, pb1;
    pa0 = *reinterpret_cast<const float4*>(Ap);
    if (BM == 128) pa1 = *reinterpret_cast<const float4*>(Ap + 4);
    pb0 = *reinterpret_cast<const float4*>(Bp);
    pb1 = *reinterpret_cast<const float4*>(Bp + (size_t)8 * Nn);
    {
        As[0][acol + 0][apr] = f2tf(pa0.x);
        As[0][acol + 1][apr] = f2tf(pa0.y);
        As[0][acol + 2][apr] = f2tf(pa0.z);
        As[0][acol + 3][apr] = f2tf(pa0.w);
        if (BM == 128) {
            As[0][acol + 4][apr] = f2tf(pa1.x);
            As[0][acol + 5][apr] = f2tf(pa1.y);
            As[0][acol + 6][apr] = f2tf(pa1.z);
            As[0][acol + 7][apr] = f2tf(pa1.w);
        }
        Bs[0][bkrow][bpr + 0] = f2tf(pb0.x);
        Bs[0][bkrow][bpr + 2] = f2tf(pb0.y);
        Bs[0][bkrow][bpr + 4] = f2tf(pb0.z);
        Bs[0][bkrow][bpr + 6] = f2tf(pb0.w);
        Bs[0][bkrow + 8][bpr + 0] = f2tf(pb1.x);
        Bs[0][bkrow + 8][bpr + 2] = f2tf(pb1.y);
        Bs[0][bkrow + 8][bpr + 4] = f2tf(pb1.z);
        Bs[0][bkrow + 8][bpr + 6] = f2tf(pb1.w);
    }
    __syncthreads();

    for (int kt = 0; kt < nt; kt++) {
        const int cur = kt & 1;
        if (kt + 1 < nt) {
            const float* ap = Ap + (size_t)(kt + 1) * BK;
            const float* bp = Bp + (size_t)(kt + 1) * BK * Nn;
            pa0 = *reinterpret_cast<const float4*>(ap);
            if (BM == 128) pa1 = *reinterpret_cast<const float4*>(ap + 4);
            pb0 = *reinterpret_cast<const float4*>(bp);
            pb1 = *reinterpret_cast<const float4*>(bp + (size_t)8 * Nn);
        }

#pragma unroll
        for (int ks = 0; ks < 2; ks++) {
            const int k0 = ks * 8;
            uint2 a0[MF], a4[MF];
#pragma unroll
            for (int mf = 0; mf < MF; mf++) {
                const int mb = wm + mf * 16 + 2 * g;
                a0[mf] = *reinterpret_cast<const uint2*>(&As[cur][k0 + c][mb]);
                a4[mf] = *reinterpret_cast<const uint2*>(&As[cur][k0 + c + 4][mb]);
            }
            uint2 b0[2], b4[2];
#pragma unroll
            for (int pg = 0; pg < 2; pg++) {
                const int nb = wn + pg * 16 + 2 * g;
                b0[pg] = *reinterpret_cast<const uint2*>(&Bs[cur][k0 + c][nb]);
                b4[pg] = *reinterpret_cast<const uint2*>(&Bs[cur][k0 + c + 4][nb]);
            }
#pragma unroll
            for (int mf = 0; mf < MF; mf++) {
                uint32_t af[4] = {a0[mf].x, a0[mf].y, a4[mf].x, a4[mf].y};
#pragma unroll
                for (int nf = 0; nf < 4; nf++) {
                    uint32_t bf[2];
                    bf[0] = (nf & 1) ? b0[nf >> 1].y : b0[nf >> 1].x;
                    bf[1] = (nf & 1) ? b4[nf >> 1].y : b4[nf >> 1].x;
                    mma_tf32(acc[mf][nf], af, bf);
                }
            }
        }

        if (kt + 1 < nt) {
            const int nxt = cur ^ 1;
            As[nxt][acol + 0][apr] = f2tf(pa0.x);
            As[nxt][acol + 1][apr] = f2tf(pa0.y);
            As[nxt][acol + 2][apr] = f2tf(pa0.z);
            As[nxt][acol + 3][apr] = f2tf(pa0.w);
            if (BM == 128) {
                As[nxt][acol + 4][apr] = f2tf(pa1.x);
                As[nxt][acol + 5][apr] = f2tf(pa1.y);
                As[nxt][acol + 6][apr] = f2tf(pa1.z);
                As[nxt][acol + 7][apr] = f2tf(pa1.w);
            }
            Bs[nxt][bkrow][bpr + 0] = f2tf(pb0.x);
            Bs[nxt][bkrow][bpr + 2] = f2tf(pb0.y);
            Bs[nxt][bkrow][bpr + 4] = f2tf(pb0.z);
            Bs[nxt][bkrow][bpr + 6] = f2tf(pb0.w);
            Bs[nxt][bkrow + 8][bpr + 0] = f2tf(pb1.x);
            Bs[nxt][bkrow + 8][bpr + 2] = f2tf(pb1.y);
            Bs[nxt][bkrow + 8][bpr + 4] = f2tf(pb1.z);
            Bs[nxt][bkrow + 8][bpr + 6] = f2tf(pb1.w);
            __syncthreads();
        }
    }

    // Epilogue: C fragment c0:(g,2c) c1:(g,2c+1) c2:(g+8,2c) c3:(g+8,2c+1)
#pragma unroll
    for (int mf = 0; mf < MF; mf++) {
#pragma unroll
        for (int nf = 0; nf < 4; nf++) {
            int row = by * BM + wm + mf * 16 + g;
            int col = bx * 128 + wn + nf * 8 + 2 * c;
#pragma unroll
            for (int half = 0; half < 2; half++) {
                int r = row + half * 8;
                float v0 = acc[mf][nf][half * 2 + 0];
                float v1 = acc[mf][nf][half * 2 + 1];
                if (EPI == 1) {
                    v0 += bias[col]     + res[(size_t)r * Nn + col];
                    v1 += bias[col + 1] + res[(size_t)r * Nn + col + 1];
                }
                if (EPI == 2) {
                    v0 += res[(size_t)r * Nn + col];
                    v1 += res[(size_t)r * Nn + col + 1];
                }
                if (EPI == 3) {
                    v0 = 0.5f * v0 * (1.f + erff(v0 * 0.70710678f));
                    v1 = 0.5f * v1 * (1.f + erff(v1 * 0.70710678f));
                }
                float2 o = make_float2(v0, v1);
                *reinterpret_cast<float2*>(C + (size_t)r * Nn + col) = o;
            }
        }
    }
}

// ---------------------------------------------------------------------------
// Tiled attention, shuffle-light version (unchanged).
// ---------------------------------------------------------------------------
template <int CROSS>
__global__ __launch_bounds__(256) void attn_kernel(
    const float* __restrict__ qsrc, const float* __restrict__ kv0,
    const float* __restrict__ kv1, float* __restrict__ out)
{
    const int OFF     = CROSS ? PFX : 0;
    const int QSTRIDE = CROSS ? INNER : 3 * INNER;

    const int hbase = blockIdx.y * DHEAD;
    const int qbase = blockIdx.x * 64;
    const int wid = threadIdx.x >> 5, lane = threadIdx.x & 31;
    const int ibase = qbase + wid * 8;

    __shared__ float Qs[64][64];
    __shared__ float KT[64][33];
    __shared__ float Vs[32][64];
    __shared__ float Ps[8][8][32];

    {
        int qr = threadIdx.x >> 2;
        int c0 = (threadIdx.x & 3) * 4;
        const float* qp = qsrc + (size_t)(qbase + qr) * QSTRIDE + hbase;
#pragma unroll
        for (int u = 0; u < 4; u++) {
            float4 v = *reinterpret_cast<const float4*>(qp + c0 + u * 16);
            Qs[qr][c0 + u * 16 + 0] = v.x * 0.125f;
            Qs[qr][c0 + u * 16 + 1] = v.y * 0.125f;
            Qs[qr][c0 + u * 16 + 2] = v.z * 0.125f;
            Qs[qr][c0 + u * 16 + 3] = v.w * 0.125f;
        }
    }

    float m[8], den[8], acc0[8], acc1[8], cs[8];
#pragma unroll
    for (int qq = 0; qq < 8; qq++) {
        m[qq] = -3.0e38f; den[qq] = 0.f; acc0[qq] = 0.f; acc1[qq] = 0.f;
    }

    const int kmax   = qbase + 63 + OFF + 1;
    const int nfull  = (qbase + OFF + 1) / 32;
    const int ntiles = (kmax + 31) / 32;

    for (int t = 0; t < ntiles; t++) {
        const int jt = t * 32;
        __syncthreads();
        {
            int key = threadIdx.x >> 3;
            int d0  = (threadIdx.x & 7) * 8;
            int j = jt + key;
            const float *kp, *vp;
            if (CROSS) {
                const float* base = (j < PFX) ? (kv0 + (size_t)j * 2048)
                                              : (kv1 + (size_t)(j - PFX) * 2048);
                kp = base + hbase; vp = base + INNER + hbase;
            } else {
                kp = kv0 + (size_t)j * 3072 + INNER + hbase;
                vp = kp + INNER;
            }
            float4 ka = *reinterpret_cast<const float4*>(kp + d0);
            float4 kb = *reinterpret_cast<const float4*>(kp + d0 + 4);
            KT[d0 + 0][key] = ka.x; KT[d0 + 1][key] = ka.y;
            KT[d0 + 2][key] = ka.z; KT[d0 + 3][key] = ka.w;
            KT[d0 + 4][key] = kb.x; KT[d0 + 5][key] = kb.y;
            KT[d0 + 6][key] = kb.z; KT[d0 + 7][key] = kb.w;
            *reinterpret_cast<float4*>(&Vs[key][d0])     =
                *reinterpret_cast<const float4*>(vp + d0);
            *reinterpret_cast<float4*>(&Vs[key][d0 + 4]) =
                *reinterpret_cast<const float4*>(vp + d0 + 4);
        }
        __syncthreads();

        float s[8];
#pragma unroll
        for (int qq = 0; qq < 8; qq++) s[qq] = 0.f;
#pragma unroll
        for (int dv = 0; dv < 16; dv++) {
            const int d = dv * 4;
            float k0 = KT[d + 0][lane];
            float k1 = KT[d + 1][lane];
            float k2 = KT[d + 2][lane];
            float k3 = KT[d + 3][lane];
#pragma unroll
            for (int qq = 0; qq < 8; qq++) {
                float4 q4 = *reinterpret_cast<const float4*>(&Qs[wid * 8 + qq][d]);
                s[qq] += q4.x * k0 + q4.y * k1 + q4.z * k2 + q4.w * k3;
            }
        }

        const bool bound = (t >= nfull);
#pragma unroll
        for (int qq = 0; qq < 8; qq++) {
            float sv = s[qq];
            if (bound && (jt + lane > ibase + qq + OFF)) sv = -3.0e38f;
            float mx = sv;
#pragma unroll
            for (int o = 16; o; o >>= 1)
                mx = fmaxf(mx, __shfl_xor_sync(0xffffffffu, mx, o));
            float mn = fmaxf(m[qq], mx);
            float cc = __expf(m[qq] - mn);
            float p  = __expf(sv - mn);
            den[qq] = den[qq] * cc + p;
            cs[qq] = cc;
            m[qq] = mn;
            Ps[wid][qq][lane] = p;
        }
        __syncwarp();

#pragma unroll
        for (int qq = 0; qq < 8; qq++) { acc0[qq] *= cs[qq]; acc1[qq] *= cs[qq]; }
#pragma unroll 4
        for (int k = 0; k < 32; k++) {
            float v0 = Vs[k][lane], v1 = Vs[k][lane + 32];
#pragma unroll
            for (int qq = 0; qq < 8; qq++) {
                float p = Ps[wid][qq][k];
                acc0[qq] += p * v0;
                acc1[qq] += p * v1;
            }
        }
    }

#pragma unroll
    for (int qq = 0; qq < 8; qq++) {
        float d = den[qq];
#pragma unroll
        for (int o = 16; o; o >>= 1)
            d += __shfl_xor_sync(0xffffffffu, d, o);
        float r = 1.f / d;
        out[(size_t)(ibase + qq) * INNER + hbase + lane]      = acc0[qq] * r;
        out[(size_t)(ibase + qq) * INNER + hbase + lane + 32] = acc1[qq] * r;
    }
}

// ---------------------------------------------------------------------------
// Host orchestration
// ---------------------------------------------------------------------------
static void run_sgemm(int epi, const float* A, const float* B, float* C,
                      const float* bias, const float* res, int M, int Nn, int K)
{
    int g128 = (Nn / 128) * (M / 128);
    if (g128 < 148) {
        // under-filled chip at BM=128: halve M-tile to double block count
        dim3 grid(Nn / 128, M / 64);
        switch (epi) {
            case 0: sgemm_kernel<64,0><<<grid, 256>>>(A, B, C, bias, res, M, Nn, K); break;
            case 1: sgemm_kernel<64,1><<<grid, 256>>>(A, B, C, bias, res, M, Nn, K); break;
            case 2: sgemm_kernel<64,2><<<grid, 256>>>(A, B, C, bias, res, M, Nn, K); break;
            case 3: sgemm_kernel<64,3><<<grid, 256>>>(A, B, C, bias, res, M, Nn, K); break;
        }
    } else {
        dim3 grid(Nn / 128, M / 128);
        switch (epi) {
            case 0: sgemm_kernel<128,0><<<grid, 256>>>(A, B, C, bias, res, M, Nn, K); break;
            case 1: sgemm_kernel<128,1><<<grid, 256>>>(A, B, C, bias, res, M, Nn, K); break;
            case 2: sgemm_kernel<128,2><<<grid, 256>>>(A, B, C, bias, res, M, Nn, K); break;
            case 3: sgemm_kernel<128,3><<<grid, 256>>>(A, B, C, bias, res, M, Nn, K); break;
        }
    }
}

extern "C" void kernel_launch(void* const* d_in, const int* in_sizes, int n_in,
                              void* d_out, int out_size)
{
    (void)in_sizes; (void)n_in; (void)out_size;

    const int*   x        = (const int*)  d_in[0];
    const float* tok_emb  = (const float*)d_in[1];
    const float* pos_emb  = (const float*)d_in[2];
    const float* ca_ln_g  = (const float*)d_in[3];
    const float* ca_ln_b  = (const float*)d_in[4];
    const float* ca_wq    = (const float*)d_in[5];
    const float* ca_wkv   = (const float*)d_in[6];
    const float* ca_wo    = (const float*)d_in[7];
    const float* ca_bo    = (const float*)d_in[8];
    const float* cf_ln_g  = (const float*)d_in[9];
    const float* cf_ln_b  = (const float*)d_in[10];
    const float* cf_w1    = (const float*)d_in[11];
    const float* cf_w2    = (const float*)d_in[12];
    const float* la_ln_g  = (const float*)d_in[13];
    const float* la_ln_b  = (const float*)d_in[14];
    const float* la_wqkv  = (const float*)d_in[15];
    const float* la_wo    = (const float*)d_in[16];
    const float* lf_ln_g  = (const float*)d_in[17];
    const float* lf_ln_b  = (const float*)d_in[18];
    const float* lf_w1    = (const float*)d_in[19];
    const float* lf_w2    = (const float*)d_in[20];
    const float* w_logits = (const float*)d_in[21];
    float* out = (float*)d_out;

    float *prefix, *h, *xn, *q, *kvin, *kvctx, *attn, *ff, *qkv;
    cudaGetSymbolAddress((void**)&prefix, g_prefix);
    cudaGetSymbolAddress((void**)&h,      g_h);
    cudaGetSymbolAddress((void**)&xn,     g_xn);
    cudaGetSymbolAddress((void**)&q,      g_q);
    cudaGetSymbolAddress((void**)&kvin,   g_kvin);
    cudaGetSymbolAddress((void**)&kvctx,  g_kvctx);
    cudaGetSymbolAddress((void**)&attn,   g_attn);
    cudaGetSymbolAddress((void**)&ff,     g_ff);
    cudaGetSymbolAddress((void**)&qkv,    g_qkv);

    // 1. Embedding
    embed_kernel<<<(NCTX * DMODEL) / 256, 256>>>(x, tok_emb, pos_emb);

    // 2. Cross-attention block
    ln_kernel<<<LAT, 256>>>(h, xn, ca_ln_g, ca_ln_b);
    run_sgemm(0, xn,     ca_wq,  q,     nullptr, nullptr, LAT, INNER,     DMODEL);
    run_sgemm(0, xn,     ca_wkv, kvin,  nullptr, nullptr, LAT, 2 * INNER, DMODEL);
    run_sgemm(0, prefix, ca_wkv, kvctx, nullptr, nullptr, PFX, 2 * INNER, DMODEL);
    {
        dim3 g(LAT / 64, NHEAD);
        attn_kernel<1><<<g, 256>>>(q, kvctx, kvin, attn);
    }
    run_sgemm(1, attn, ca_wo, h, ca_bo, h, LAT, DMODEL, INNER);

    // 3. Cross FFN
    ln_kernel<<<LAT, 256>>>(h, xn, cf_ln_g, cf_ln_b);
    run_sgemm(3, xn, cf_w1, ff, nullptr, nullptr, LAT, FFDIM, DMODEL);
    run_sgemm(2, ff, cf_w2, h, nullptr, h, LAT, DMODEL, FFDIM);

    // 4. Latent self-attention layers
    for (int l = 0; l < DEPTH; l++) {
        ln_kernel<<<LAT, 256>>>(h, xn, la_ln_g + (size_t)l * DMODEL, la_ln_b + (size_t)l * DMODEL);
        run_sgemm(0, xn, la_wqkv + (size_t)l * DMODEL * 3 * INNER, qkv,
                  nullptr, nullptr, LAT, 3 * INNER, DMODEL);
        {
            dim3 g(LAT / 64, NHEAD);
            attn_kernel<0><<<g, 256>>>(qkv, qkv, nullptr, attn);
        }
        run_sgemm(2, attn, la_wo + (size_t)l * INNER * DMODEL, h, nullptr, h, LAT, DMODEL, INNER);

        ln_kernel<<<LAT, 256>>>(h, xn, lf_ln_g + (size_t)l * DMODEL, lf_ln_b + (size_t)l * DMODEL);
        run_sgemm(3, xn, lf_w1 + (size_t)l * DMODEL * FFDIM, ff, nullptr, nullptr, LAT, FFDIM, DMODEL);
        run_sgemm(2, ff, lf_w2 + (size_t)l * FFDIM * DMODEL, h, nullptr, h, LAT, DMODEL, FFDIM);
    }

    // 5. Logits
    run_sgemm(0, h, w_logits, out, nullptr, nullptr, LAT, VOCAB, DMODEL);
}

// round 10
// speedup vs baseline: 1.1779x; 1.1779x over previous
#include <cuda_runtime.h>
#include <cuda_bf16.h>
#include <math.h>
#include <stdint.h>

// Problem constants
#define NCTX   4096
#define DMODEL 1024
#define NHEAD  16
#define DHEAD  64
#define DEPTH  4
#define PFX    3072
#define LAT    1024          // NCTX - PFX
#define FFDIM  4096
#define VOCAB  32000
#define INNER  1024          // NHEAD * DHEAD

// ---------------------------------------------------------------------------
// Scratch (static __device__ globals; no runtime allocation)
// ---------------------------------------------------------------------------
__device__ float g_prefix[PFX * DMODEL];
__device__ float g_h     [LAT * DMODEL];
__device__ float g_xn    [LAT * DMODEL];
__device__ float g_q     [LAT * INNER];
__device__ float g_kvin  [LAT * 2 * INNER];
__device__ float g_kvctx [PFX * 2 * INNER];
__device__ float g_attn  [LAT * INNER];
__device__ float g_ff    [LAT * FFDIM];
__device__ float g_qkv   [LAT * 3 * INNER];

// tf32-rounded weight scratch (one big buffer, float offsets)
#define W_WQ    0
#define W_WKV   (W_WQ   + DMODEL * INNER)
#define W_WO    (W_WKV  + DMODEL * 2 * INNER)
#define W_CF1   (W_WO   + INNER * DMODEL)
#define W_CF2   (W_CF1  + DMODEL * FFDIM)
#define W_LQKV  (W_CF2  + FFDIM * DMODEL)
#define W_LWO   (W_LQKV + DEPTH * DMODEL * 3 * INNER)
#define W_LF1   (W_LWO  + DEPTH * INNER * DMODEL)
#define W_LF2   (W_LF1  + DEPTH * DMODEL * FFDIM)
#define W_LOG   (W_LF2  + DEPTH * FFDIM * DMODEL)
#define W_TOTAL (W_LOG  + DMODEL * VOCAB)
__device__ float g_w[W_TOTAL];

// ---------------------------------------------------------------------------
// tf32 rounding helper
// ---------------------------------------------------------------------------
__device__ __forceinline__ uint32_t f2tf(float x) {
    uint32_t r;
    asm("cvt.rna.tf32.f32 %0, %1;" : "=r"(r) : "f"(x));
    return r;
}
__device__ __forceinline__ float rnd_tf32(float x) {
    return __uint_as_float(f2tf(x));
}

// ---------------------------------------------------------------------------
// Elementwise tf32 rounding pass (float4)
// ---------------------------------------------------------------------------
__global__ void round_kernel(const float* __restrict__ in,
                             float* __restrict__ out, int n4)
{
    int i = blockIdx.x * blockDim.x + threadIdx.x;
    if (i < n4) {
        float4 v = reinterpret_cast<const float4*>(in)[i];
        v.x = rnd_tf32(v.x); v.y = rnd_tf32(v.y);
        v.z = rnd_tf32(v.z); v.w = rnd_tf32(v.w);
        reinterpret_cast<float4*>(out)[i] = v;
    }
}

// ---------------------------------------------------------------------------
// Embedding (prefix feeds GEMM only -> pre-rounded; h stays fp32)
// ---------------------------------------------------------------------------
__global__ void embed_kernel(const int* __restrict__ x,
                             const float* __restrict__ tok,
                             const float* __restrict__ pos)
{
    int idx = blockIdx.x * blockDim.x + threadIdx.x;
    int n = idx >> 10;
    int d = idx & 1023;
    float v = tok[(size_t)x[n] * DMODEL + d] + pos[idx];
    if (n < PFX) g_prefix[(size_t)n * DMODEL + d] = rnd_tf32(v);
    else         g_h[(size_t)(n - PFX) * DMODEL + d] = v;
}

// ---------------------------------------------------------------------------
// LayerNorm (D=1024); output feeds GEMM A only -> pre-rounded to tf32
// ---------------------------------------------------------------------------
__global__ __launch_bounds__(256) void ln_kernel(
    const float* __restrict__ in, float* __restrict__ out,
    const float* __restrict__ g, const float* __restrict__ b)
{
    int row = blockIdx.x;
    const float* p = in + (size_t)row * DMODEL;
    float vals[4];
    float s = 0.f, s2 = 0.f;
#pragma unroll
    for (int u = 0; u < 4; u++) {
        float v = p[threadIdx.x + u * 256];
        vals[u] = v; s += v; s2 += v * v;
    }
#pragma unroll
    for (int o = 16; o; o >>= 1) {
        s  += __shfl_xor_sync(0xffffffffu, s,  o);
        s2 += __shfl_xor_sync(0xffffffffu, s2, o);
    }
    __shared__ float sh[2][8];
    int wid = threadIdx.x >> 5, lane = threadIdx.x & 31;
    if (lane == 0) { sh[0][wid] = s; sh[1][wid] = s2; }
    __syncthreads();
    s = 0.f; s2 = 0.f;
#pragma unroll
    for (int w = 0; w < 8; w++) { s += sh[0][w]; s2 += sh[1][w]; }
    float mean = s * (1.f / DMODEL);
    float var  = s2 * (1.f / DMODEL) - mean * mean;
    float inv  = rsqrtf(var + 1e-5f);
#pragma unroll
    for (int u = 0; u < 4; u++) {
        int d = threadIdx.x + u * 256;
        out[(size_t)row * DMODEL + d] =
            rnd_tf32((vals[u] - mean) * inv * g[d] + b[d]);
    }
}

// ---------------------------------------------------------------------------
// TF32 tensor-core GEMM with cp.async 3-stage pipeline.
// Inputs MUST already be tf32-rounded (values with low 13 mantissa bits 0).
// C[M,N] = A[M,K] @ B[K,N], row-major. mma.sync.m16n8k8 tf32, fp32 acc.
// Block tile BMx128, BK=16, 256 threads = 8 warps (2M x 4N).
// Smem: A [m][k] pitch 20 (conflict-free frag loads), B [k][n] pitch 136.
// One __syncthreads per k-tile; cp.async.cg 16B; wait_group<1>.
// Epilogues: 0 none | 1 +bias[col]+res | 2 +res | 3 exact GELU (tf32-rounded)
// ---------------------------------------------------------------------------
#define BK 16
#define STAGES 3

__device__ __forceinline__ uint32_t smem_u32(const void* p) {
    return static_cast<uint32_t>(__cvta_generic_to_shared(p));
}

__device__ __forceinline__ void mma_tf32(float* d, const uint32_t* a, const uint32_t* b) {
    asm volatile(
        "mma.sync.aligned.m16n8k8.row.col.f32.tf32.tf32.f32 "
        "{%0,%1,%2,%3}, {%4,%5,%6,%7}, {%8,%9}, {%0,%1,%2,%3};"
        : "+f"(d[0]), "+f"(d[1]), "+f"(d[2]), "+f"(d[3])
        : "r"(a[0]), "r"(a[1]), "r"(a[2]), "r"(a[3]), "r"(b[0]), "r"(b[1]));
}

template <int BM, int EPI>
__global__ __launch_bounds__(256, 2) void sgemm_kernel(
    const float* __restrict__ A, const float* __restrict__ B,
    float* __restrict__ C, const float* __restrict__ bias,
    const float* __restrict__ res, int M, int Nn, int K)
{
    constexpr int MF = BM / 32;   // m-fragments per warp
    constexpr int AP = 20;        // A smem pitch: (20g+c)%32 all-distinct
    constexpr int BP = 136;       // B smem pitch: (8c+g)%32 all-distinct
    extern __shared__ __align__(16) float smem[];
    float* As = smem;                          // [STAGES][BM][AP]
    float* Bs = smem + STAGES * BM * AP;       // [STAGES][BK][BP]

    const int tid  = threadIdx.x;
    const int lane = tid & 31, wid = tid >> 5;
    const int g = lane >> 2, c = lane & 3;
    const int wm = (wid & 1) * (BM / 2);
    const int wn = (wid >> 1) * 32;
    const int bx = blockIdx.x, by = blockIdx.y;

    const int nt = K / BK;

    auto issue_stage = [&](int kt, int slot) {
        const float* Ag = A + (size_t)(by * BM) * K + kt * BK;
#pragma unroll
        for (int r = 0; r < (BM * 4) / 256; r++) {
            int ch = tid + r * 256;
            int m = ch >> 2, ko = (ch & 3) << 2;
            uint32_t dst = smem_u32(&As[(slot * BM + m) * AP + ko]);
            const float* src = Ag + (size_t)m * K + ko;
            asm volatile("cp.async.cg.shared.global [%0], [%1], 16;"
                         :: "r"(dst), "l"(src) : "memory");
        }
        const float* Bg = B + (size_t)(kt * BK) * Nn + bx * 128;
#pragma unroll
        for (int r = 0; r < 2; r++) {
            int ch = tid + r * 256;
            int kr = ch >> 5, no = (ch & 31) << 2;
            uint32_t dst = smem_u32(&Bs[(slot * BK + kr) * BP + no]);
            const float* src = Bg + (size_t)kr * Nn + no;
            asm volatile("cp.async.cg.shared.global [%0], [%1], 16;"
                         :: "r"(dst), "l"(src) : "memory");
        }
        asm volatile("cp.async.commit_group;" ::: "memory");
    };

    float acc[MF][4][4];
#pragma unroll
    for (int mf = 0; mf < MF; mf++)
#pragma unroll
        for (int nf = 0; nf < 4; nf++)
#pragma unroll
            for (int i = 0; i < 4; i++) acc[mf][nf][i] = 0.f;

    // prologue: 2 stages in flight
#pragma unroll
    for (int s = 0; s < STAGES - 1; s++) issue_stage(s, s);

    for (int kt = 0; kt < nt; kt++) {
        // stage kt complete when at most 1 (newest) group pending
        asm volatile("cp.async.wait_group %0;" :: "n"(STAGES - 2) : "memory");
        __syncthreads();
        // all threads are past compute(kt-1): safe to overwrite slot (kt-1)%3
        if (kt + STAGES - 1 < nt)
            issue_stage(kt + STAGES - 1, (kt + STAGES - 1) % STAGES);
        else
            asm volatile("cp.async.commit_group;" ::: "memory"); // keep count

        const int slot = kt % STAGES;
        const uint32_t* Asl = reinterpret_cast<const uint32_t*>(&As[slot * BM * AP]);
        const uint32_t* Bsl = reinterpret_cast<const uint32_t*>(&Bs[slot * BK * BP]);

#pragma unroll
        for (int ks = 0; ks < 2; ks++) {
            const int k0 = ks * 8;
            uint32_t af[MF][4], bf[4][2];
#pragma unroll
            for (int mf = 0; mf < MF; mf++) {
                const int mrow = wm + mf * 16 + g;
                af[mf][0] = Asl[(size_t)mrow * AP + k0 + c];
                af[mf][1] = Asl[(size_t)(mrow + 8) * AP + k0 + c];
                af[mf][2] = Asl[(size_t)mrow * AP + k0 + c + 4];
                af[mf][3] = Asl[(size_t)(mrow + 8) * AP + k0 + c + 4];
            }
#pragma unroll
            for (int nf = 0; nf < 4; nf++) {
                const int ncol = wn + nf * 8 + g;
                bf[nf][0] = Bsl[(size_t)(k0 + c) * BP + ncol];
                bf[nf][1] = Bsl[(size_t)(k0 + c + 4) * BP + ncol];
            }
#pragma unroll
            for (int mf = 0; mf < MF; mf++)
#pragma unroll
                for (int nf = 0; nf < 4; nf++)
                    mma_tf32(acc[mf][nf], af[mf], bf[nf]);
        }
    }

    // Epilogue: C fragment c0:(g,2c) c1:(g,2c+1) c2:(g+8,2c) c3:(g+8,2c+1)
#pragma unroll
    for (int mf = 0; mf < MF; mf++) {
#pragma unroll
        for (int nf = 0; nf < 4; nf++) {
            int row = by * BM + wm + mf * 16 + g;
            int col = bx * 128 + wn + nf * 8 + 2 * c;
#pragma unroll
            for (int half = 0; half < 2; half++) {
                int r = row + half * 8;
                float v0 = acc[mf][nf][half * 2 + 0];
                float v1 = acc[mf][nf][half * 2 + 1];
                if (EPI == 1) {
                    v0 += bias[col]     + res[(size_t)r * Nn + col];
                    v1 += bias[col + 1] + res[(size_t)r * Nn + col + 1];
                }
                if (EPI == 2) {
                    v0 += res[(size_t)r * Nn + col];
                    v1 += res[(size_t)r * Nn + col + 1];
                }
                if (EPI == 3) {
                    v0 = 0.5f * v0 * (1.f + erff(v0 * 0.70710678f));
                    v1 = 0.5f * v1 * (1.f + erff(v1 * 0.70710678f));
                    v0 = rnd_tf32(v0);   // ff feeds next GEMM's A
                    v1 = rnd_tf32(v1);
                }
                float2 o = make_float2(v0, v1);
                *reinterpret_cast<float2*>(C + (size_t)r * Nn + col) = o;
            }
        }
    }
}

// ---------------------------------------------------------------------------
// Tiled attention, shuffle-light (unchanged math; output tf32-rounded since
// it feeds the wo GEMM's A operand).
// ---------------------------------------------------------------------------
template <int CROSS>
__global__ __launch_bounds__(256) void attn_kernel(
    const float* __restrict__ qsrc, const float* __restrict__ kv0,
    const float* __restrict__ kv1, float* __restrict__ out)
{
    const int OFF     = CROSS ? PFX : 0;
    const int QSTRIDE = CROSS ? INNER : 3 * INNER;

    const int hbase = blockIdx.y * DHEAD;
    const int qbase = blockIdx.x * 64;
    const int wid = threadIdx.x >> 5, lane = threadIdx.x & 31;
    const int ibase = qbase + wid * 8;

    __shared__ float Qs[64][64];
    __shared__ float KT[64][33];
    __shared__ float Vs[32][64];
    __shared__ float Ps[8][8][32];

    {
        int qr = threadIdx.x >> 2;
        int c0 = (threadIdx.x & 3) * 4;
        const float* qp = qsrc + (size_t)(qbase + qr) * QSTRIDE + hbase;
#pragma unroll
        for (int u = 0; u < 4; u++) {
            float4 v = *reinterpret_cast<const float4*>(qp + c0 + u * 16);
            Qs[qr][c0 + u * 16 + 0] = v.x * 0.125f;
            Qs[qr][c0 + u * 16 + 1] = v.y * 0.125f;
            Qs[qr][c0 + u * 16 + 2] = v.z * 0.125f;
            Qs[qr][c0 + u * 16 + 3] = v.w * 0.125f;
        }
    }

    float m[8], den[8], acc0[8], acc1[8], cs[8];
#pragma unroll
    for (int qq = 0; qq < 8; qq++) {
        m[qq] = -3.0e38f; den[qq] = 0.f; acc0[qq] = 0.f; acc1[qq] = 0.f;
    }

    const int kmax   = qbase + 63 + OFF + 1;
    const int nfull  = (qbase + OFF + 1) / 32;
    const int ntiles = (kmax + 31) / 32;

    for (int t = 0; t < ntiles; t++) {
        const int jt = t * 32;
        __syncthreads();
        {
            int key = threadIdx.x >> 3;
            int d0  = (threadIdx.x & 7) * 8;
            int j = jt + key;
            const float *kp, *vp;
            if (CROSS) {
                const float* base = (j < PFX) ? (kv0 + (size_t)j * 2048)
                                              : (kv1 + (size_t)(j - PFX) * 2048);
                kp = base + hbase; vp = base + INNER + hbase;
            } else {
                kp = kv0 + (size_t)j * 3072 + INNER + hbase;
                vp = kp + INNER;
            }
            float4 ka = *reinterpret_cast<const float4*>(kp + d0);
            float4 kb = *reinterpret_cast<const float4*>(kp + d0 + 4);
            KT[d0 + 0][key] = ka.x; KT[d0 + 1][key] = ka.y;
            KT[d0 + 2][key] = ka.z; KT[d0 + 3][key] = ka.w;
            KT[d0 + 4][key] = kb.x; KT[d0 + 5][key] = kb.y;
            KT[d0 + 6][key] = kb.z; KT[d0 + 7][key] = kb.w;
            *reinterpret_cast<float4*>(&Vs[key][d0])     =
                *reinterpret_cast<const float4*>(vp + d0);
            *reinterpret_cast<float4*>(&Vs[key][d0 + 4]) =
                *reinterpret_cast<const float4*>(vp + d0 + 4);
        }
        __syncthreads();

        float s[8];
#pragma unroll
        for (int qq = 0; qq < 8; qq++) s[qq] = 0.f;
#pragma unroll
        for (int dv = 0; dv < 16; dv++) {
            const int d = dv * 4;
            float k0 = KT[d + 0][lane];
            float k1 = KT[d + 1][lane];
            float k2 = KT[d + 2][lane];
            float k3 = KT[d + 3][lane];
#pragma unroll
            for (int qq = 0; qq < 8; qq++) {
                float4 q4 = *reinterpret_cast<const float4*>(&Qs[wid * 8 + qq][d]);
                s[qq] += q4.x * k0 + q4.y * k1 + q4.z * k2 + q4.w * k3;
            }
        }

        const bool bound = (t >= nfull);
#pragma unroll
        for (int qq = 0; qq < 8; qq++) {
            float sv = s[qq];
            if (bound && (jt + lane > ibase + qq + OFF)) sv = -3.0e38f;
            float mx = sv;
#pragma unroll
            for (int o = 16; o; o >>= 1)
                mx = fmaxf(mx, __shfl_xor_sync(0xffffffffu, mx, o));
            float mn = fmaxf(m[qq], mx);
            float cc = __expf(m[qq] - mn);
            float p  = __expf(sv - mn);
            den[qq] = den[qq] * cc + p;
            cs[qq] = cc;
            m[qq] = mn;
            Ps[wid][qq][lane] = p;
        }
        __syncwarp();

#pragma unroll
        for (int qq = 0; qq < 8; qq++) { acc0[qq] *= cs[qq]; acc1[qq] *= cs[qq]; }
#pragma unroll 4
        for (int k = 0; k < 32; k++) {
            float v0 = Vs[k][lane], v1 = Vs[k][lane + 32];
#pragma unroll
            for (int qq = 0; qq < 8; qq++) {
                float p = Ps[wid][qq][k];
                acc0[qq] += p * v0;
                acc1[qq] += p * v1;
            }
        }
    }

#pragma unroll
    for (int qq = 0; qq < 8; qq++) {
        float d = den[qq];
#pragma unroll
        for (int o = 16; o; o >>= 1)
            d += __shfl_xor_sync(0xffffffffu, d, o);
        float r = 1.f / d;
        out[(size_t)(ibase + qq) * INNER + hbase + lane]      = rnd_tf32(acc0[qq] * r);
        out[(size_t)(ibase + qq) * INNER + hbase + lane + 32] = rnd_tf32(acc1[qq] * r);
    }
}

// ---------------------------------------------------------------------------
// Host orchestration
// ---------------------------------------------------------------------------
static const int SMEM128 = (STAGES * (128 * 20 + BK * 136)) * 4; // 56832 B
static const int SMEM64  = (STAGES * ( 64 * 20 + BK * 136)) * 4; // 41472 B

static void run_sgemm(int epi, const float* A, const float* B, float* C,
                      const float* bias, const float* res, int M, int Nn, int K)
{
    int g128 = (Nn / 128) * (M / 128);
    if (g128 <= 64) {
        dim3 grid(Nn / 128, M / 64);
        switch (epi) {
            case 0: sgemm_kernel<64,0><<<grid, 256, SMEM64>>>(A, B, C, bias, res, M, Nn, K); break;
            case 1: sgemm_kernel<64,1><<<grid, 256, SMEM64>>>(A, B, C, bias, res, M, Nn, K); break;
            case 2: sgemm_kernel<64,2><<<grid, 256, SMEM64>>>(A, B, C, bias, res, M, Nn, K); break;
            case 3: sgemm_kernel<64,3><<<grid, 256, SMEM64>>>(A, B, C, bias, res, M, Nn, K); break;
        }
    } else {
        dim3 grid(Nn / 128, M / 128);
        switch (epi) {
            case 0: sgemm_kernel<128,0><<<grid, 256, SMEM128>>>(A, B, C, bias, res, M, Nn, K); break;
            case 1: sgemm_kernel<128,1><<<grid, 256, SMEM128>>>(A, B, C, bias, res, M, Nn, K); break;
            case 2: sgemm_kernel<128,2><<<grid, 256, SMEM128>>>(A, B, C, bias, res, M, Nn, K); break;
            case 3: sgemm_kernel<128,3><<<grid, 256, SMEM128>>>(A, B, C, bias, res, M, Nn, K); break;
        }
    }
}

static void run_round(const float* src, float* dst, size_t n)
{
    int n4 = (int)(n / 4);
    round_kernel<<<(n4 + 255) / 256, 256>>>(src, dst, n4);
}

extern "C" void kernel_launch(void* const* d_in, const int* in_sizes, int n_in,
                              void* d_out, int out_size)
{
    (void)in_sizes; (void)n_in; (void)out_size;

    const int*   x        = (const int*)  d_in[0];
    const float* tok_emb  = (const float*)d_in[1];
    const float* pos_emb  = (const float*)d_in[2];
    const float* ca_ln_g  = (const float*)d_in[3];
    const float* ca_ln_b  = (const float*)d_in[4];
    const float* ca_wq    = (const float*)d_in[5];
    const float* ca_wkv   = (const float*)d_in[6];
    const float* ca_wo    = (const float*)d_in[7];
    const float* ca_bo    = (const float*)d_in[8];
    const float* cf_ln_g  = (const float*)d_in[9];
    const float* cf_ln_b  = (const float*)d_in[10];
    const float* cf_w1    = (const float*)d_in[11];
    const float* cf_w2    = (const float*)d_in[12];
    const float* la_ln_g  = (const float*)d_in[13];
    const float* la_ln_b  = (const float*)d_in[14];
    const float* la_wqkv  = (const float*)d_in[15];
    const float* la_wo    = (const float*)d_in[16];
    const float* lf_ln_g  = (const float*)d_in[17];
    const float* lf_ln_b  = (const float*)d_in[18];
    const float* lf_w1    = (const float*)d_in[19];
    const float* lf_w2    = (const float*)d_in[20];
    const float* w_logits = (const float*)d_in[21];
    float* out = (float*)d_out;

    // Opt-in to >48KB dynamic smem for the BM128 instantiations (idempotent).
    cudaFuncSetAttribute(sgemm_kernel<128,0>, cudaFuncAttributeMaxDynamicSharedMemorySize, SMEM128);
    cudaFuncSetAttribute(sgemm_kernel<128,1>, cudaFuncAttributeMaxDynamicSharedMemorySize, SMEM128);
    cudaFuncSetAttribute(sgemm_kernel<128,2>, cudaFuncAttributeMaxDynamicSharedMemorySize, SMEM128);
    cudaFuncSetAttribute(sgemm_kernel<128,3>, cudaFuncAttributeMaxDynamicSharedMemorySize, SMEM128);

    float *prefix, *h, *xn, *q, *kvin, *kvctx, *attn, *ff, *qkv, *w;
    cudaGetSymbolAddress((void**)&prefix, g_prefix);
    cudaGetSymbolAddress((void**)&h,      g_h);
    cudaGetSymbolAddress((void**)&xn,     g_xn);
    cudaGetSymbolAddress((void**)&q,      g_q);
    cudaGetSymbolAddress((void**)&kvin,   g_kvin);
    cudaGetSymbolAddress((void**)&kvctx,  g_kvctx);
    cudaGetSymbolAddress((void**)&attn,   g_attn);
    cudaGetSymbolAddress((void**)&ff,     g_ff);
    cudaGetSymbolAddress((void**)&qkv,    g_qkv);
    cudaGetSymbolAddress((void**)&w,      g_w);

    // 0. Pre-round all weights to tf32 values (same values the old kernel
    //    produced with in-GEMM cvt.rna -> numerics identical).
    run_round(ca_wq,    w + W_WQ,   (size_t)DMODEL * INNER);
    run_round(ca_wkv,   w + W_WKV,  (size_t)DMODEL * 2 * INNER);
    run_round(ca_wo,    w + W_WO,   (size_t)INNER * DMODEL);
    run_round(cf_w1,    w + W_CF1,  (size_t)DMODEL * FFDIM);
    run_round(cf_w2,    w + W_CF2,  (size_t)FFDIM * DMODEL);
    run_round(la_wqkv,  w + W_LQKV, (size_t)DEPTH * DMODEL * 3 * INNER);
    run_round(la_wo,    w + W_LWO,  (size_t)DEPTH * INNER * DMODEL);
    run_round(lf_w1,    w + W_LF1,  (size_t)DEPTH * DMODEL * FFDIM);
    run_round(lf_w2,    w + W_LF2,  (size_t)DEPTH * FFDIM * DMODEL);
    run_round(w_logits, w + W_LOG,  (size_t)DMODEL * VOCAB);

    // 1. Embedding
    embed_kernel<<<(NCTX * DMODEL) / 256, 256>>>(x, tok_emb, pos_emb);

    // 2. Cross-attention block
    ln_kernel<<<LAT, 256>>>(h, xn, ca_ln_g, ca_ln_b);
    run_sgemm(0, xn,     w + W_WQ,  q,     nullptr, nullptr, LAT, INNER,     DMODEL);
    run_sgemm(0, xn,     w + W_WKV, kvin,  nullptr, nullptr, LAT, 2 * INNER, DMODEL);
    run_sgemm(0, prefix, w + W_WKV, kvctx, nullptr, nullptr, PFX, 2 * INNER, DMODEL);
    {
        dim3 gg(LAT / 64, NHEAD);
        attn_kernel<1><<<gg, 256>>>(q, kvctx, kvin, attn);
    }
    run_sgemm(1, attn, w + W_WO, h, ca_bo, h, LAT, DMODEL, INNER);

    // 3. Cross FFN
    ln_kernel<<<LAT, 256>>>(h, xn, cf_ln_g, cf_ln_b);
    run_sgemm(3, xn, w + W_CF1, ff, nullptr, nullptr, LAT, FFDIM, DMODEL);
    run_sgemm(2, ff, w + W_CF2, h, nullptr, h, LAT, DMODEL, FFDIM);

    // 4. Latent self-attention layers
    for (int l = 0; l < DEPTH; l++) {
        ln_kernel<<<LAT, 256>>>(h, xn, la_ln_g + (size_t)l * DMODEL, la_ln_b + (size_t)l * DMODEL);
        run_sgemm(0, xn, w + W_LQKV + (size_t)l * DMODEL * 3 * INNER, qkv,
                  nullptr, nullptr, LAT, 3 * INNER, DMODEL);
        {
            dim3 gg(LAT / 64, NHEAD);
            attn_kernel<0><<<gg, 256>>>(qkv, qkv, nullptr, attn);
        }
        run_sgemm(2, attn, w + W_LWO + (size_t)l * INNER * DMODEL, h, nullptr, h, LAT, DMODEL, INNER);

        ln_kernel<<<LAT, 256>>>(h, xn, lf_ln_g + (size_t)l * DMODEL, lf_ln_b + (size_t)l * DMODEL);
        run_sgemm(3, xn, w + W_LF1 + (size_t)l * DMODEL * FFDIM, ff, nullptr, nullptr, LAT, FFDIM, DMODEL);
        run_sgemm(2, ff, w + W_LF2 + (size_t)l * FFDIM * DMODEL, h, nullptr, h, LAT, DMODEL, FFDIM);
    }

    // 5. Logits (round h into xn first: h itself must stay fp32)
    run_round(h, xn, (size_t)LAT * DMODEL);
    run_sgemm(0, xn, w + W_LOG, out, nullptr, nullptr, LAT, VOCAB, DMODEL);
}

// round 11
// speedup vs baseline: 1.4315x; 1.2154x over previous
#include <cuda_runtime.h>
#include <cuda_bf16.h>
#include <math.h>
#include <stdint.h>

// Problem constants
#define NCTX   4096
#define DMODEL 1024
#define NHEAD  16
#define DHEAD  64
#define DEPTH  4
#define PFX    3072
#define LAT    1024          // NCTX - PFX
#define FFDIM  4096
#define VOCAB  32000
#define INNER  1024          // NHEAD * DHEAD

// ---------------------------------------------------------------------------
// Scratch (static __device__ globals; no runtime allocation)
// ---------------------------------------------------------------------------
__device__ float g_prefix[PFX * DMODEL];
__device__ float g_h     [LAT * DMODEL];
__device__ float g_xn    [LAT * DMODEL];
__device__ float g_kvctx [PFX * 2 * INNER];
__device__ float g_attn  [LAT * INNER];
__device__ float g_ff    [LAT * FFDIM];
__device__ float g_qkv   [LAT * 3 * INNER];

// tf32-rounded weight scratch (one big buffer, float offsets)
#define W_CQKV  0
#define W_WKV   (W_CQKV + DMODEL * 3 * INNER)
#define W_WO    (W_WKV  + DMODEL * 2 * INNER)
#define W_CF1   (W_WO   + INNER * DMODEL)
#define W_CF2   (W_CF1  + DMODEL * FFDIM)
#define W_LQKV  (W_CF2  + FFDIM * DMODEL)
#define W_LWO   (W_LQKV + DEPTH * DMODEL * 3 * INNER)
#define W_LF1   (W_LWO  + DEPTH * INNER * DMODEL)
#define W_LF2   (W_LF1  + DEPTH * DMODEL * FFDIM)
#define W_LOG   (W_LF2  + DEPTH * FFDIM * DMODEL)
#define W_TOTAL (W_LOG  + DMODEL * VOCAB)
__device__ float g_w[W_TOTAL];

// ---------------------------------------------------------------------------
// tf32 rounding helpers
// ---------------------------------------------------------------------------
__device__ __forceinline__ uint32_t f2tf(float x) {
    uint32_t r;
    asm("cvt.rna.tf32.f32 %0, %1;" : "=r"(r) : "f"(x));
    return r;
}
__device__ __forceinline__ float rnd_tf32(float x) {
    return __uint_as_float(f2tf(x));
}

// ---------------------------------------------------------------------------
// Elementwise tf32 rounding pass (float4)
// ---------------------------------------------------------------------------
__global__ void round_kernel(const float* __restrict__ in,
                             float* __restrict__ out, int n4)
{
    int i = blockIdx.x * blockDim.x + threadIdx.x;
    if (i < n4) {
        float4 v = reinterpret_cast<const float4*>(in)[i];
        v.x = rnd_tf32(v.x); v.y = rnd_tf32(v.y);
        v.z = rnd_tf32(v.z); v.w = rnd_tf32(v.w);
        reinterpret_cast<float4*>(out)[i] = v;
    }
}

// Pack [wq | wkv] -> row-major [DMODEL][3*INNER], tf32-rounded.
__global__ void pack_cqkv_kernel(const float* __restrict__ wq,
                                 const float* __restrict__ wkv,
                                 float* __restrict__ dst)
{
    int i = blockIdx.x * blockDim.x + threadIdx.x;  // over D*3I/4
    if (i >= (DMODEL * 3 * INNER) / 4) return;
    int i4 = i * 4;
    int d = i4 / (3 * INNER);
    int j = i4 % (3 * INNER);
    float4 v;
    if (j < INNER)
        v = *reinterpret_cast<const float4*>(wq + (size_t)d * INNER + j);
    else
        v = *reinterpret_cast<const float4*>(wkv + (size_t)d * 2 * INNER + (j - INNER));
    v.x = rnd_tf32(v.x); v.y = rnd_tf32(v.y);
    v.z = rnd_tf32(v.z); v.w = rnd_tf32(v.w);
    reinterpret_cast<float4*>(dst)[i] = v;
}

// ---------------------------------------------------------------------------
// Embedding (prefix feeds GEMM only -> pre-rounded; h stays fp32)
// ---------------------------------------------------------------------------
__global__ void embed_kernel(const int* __restrict__ x,
                             const float* __restrict__ tok,
                             const float* __restrict__ pos)
{
    int idx = blockIdx.x * blockDim.x + threadIdx.x;
    int n = idx >> 10;
    int d = idx & 1023;
    float v = tok[(size_t)x[n] * DMODEL + d] + pos[idx];
    if (n < PFX) g_prefix[(size_t)n * DMODEL + d] = rnd_tf32(v);
    else         g_h[(size_t)(n - PFX) * DMODEL + d] = v;
}

// ---------------------------------------------------------------------------
// LayerNorm (D=1024); output feeds GEMM A only -> pre-rounded to tf32
// ---------------------------------------------------------------------------
__global__ __launch_bounds__(256) void ln_kernel(
    const float* __restrict__ in, float* __restrict__ out,
    const float* __restrict__ g, const float* __restrict__ b)
{
    int row = blockIdx.x;
    const float* p = in + (size_t)row * DMODEL;
    float vals[4];
    float s = 0.f, s2 = 0.f;
#pragma unroll
    for (int u = 0; u < 4; u++) {
        float v = p[threadIdx.x + u * 256];
        vals[u] = v; s += v; s2 += v * v;
    }
#pragma unroll
    for (int o = 16; o; o >>= 1) {
        s  += __shfl_xor_sync(0xffffffffu, s,  o);
        s2 += __shfl_xor_sync(0xffffffffu, s2, o);
    }
    __shared__ float sh[2][8];
    int wid = threadIdx.x >> 5, lane = threadIdx.x & 31;
    if (lane == 0) { sh[0][wid] = s; sh[1][wid] = s2; }
    __syncthreads();
    s = 0.f; s2 = 0.f;
#pragma unroll
    for (int w = 0; w < 8; w++) { s += sh[0][w]; s2 += sh[1][w]; }
    float mean = s * (1.f / DMODEL);
    float var  = s2 * (1.f / DMODEL) - mean * mean;
    float inv  = rsqrtf(var + 1e-5f);
#pragma unroll
    for (int u = 0; u < 4; u++) {
        int d = threadIdx.x + u * 256;
        out[(size_t)row * DMODEL + d] =
            rnd_tf32((vals[u] - mean) * inv * g[d] + b[d]);
    }
}

// ---------------------------------------------------------------------------
// TF32 tensor-core GEMM with cp.async 3-stage pipeline (unchanged from R10).
// ---------------------------------------------------------------------------
#define BK 16
#define STAGES 3

__device__ __forceinline__ uint32_t smem_u32(const void* p) {
    return static_cast<uint32_t>(__cvta_generic_to_shared(p));
}

__device__ __forceinline__ void mma_tf32(float* d, const uint32_t* a, const uint32_t* b) {
    asm volatile(
        "mma.sync.aligned.m16n8k8.row.col.f32.tf32.tf32.f32 "
        "{%0,%1,%2,%3}, {%4,%5,%6,%7}, {%8,%9}, {%0,%1,%2,%3};"
        : "+f"(d[0]), "+f"(d[1]), "+f"(d[2]), "+f"(d[3])
        : "r"(a[0]), "r"(a[1]), "r"(a[2]), "r"(a[3]), "r"(b[0]), "r"(b[1]));
}

template <int BM, int EPI>
__global__ __launch_bounds__(256, 2) void sgemm_kernel(
    const float* __restrict__ A, const float* __restrict__ B,
    float* __restrict__ C, const float* __restrict__ bias,
    const float* __restrict__ res, int M, int Nn, int K)
{
    constexpr int MF = BM / 32;
    constexpr int AP = 20;
    constexpr int BP = 136;
    extern __shared__ __align__(16) float smem[];
    float* As = smem;
    float* Bs = smem + STAGES * BM * AP;

    const int tid  = threadIdx.x;
    const int lane = tid & 31, wid = tid >> 5;
    const int g = lane >> 2, c = lane & 3;
    const int wm = (wid & 1) * (BM / 2);
    const int wn = (wid >> 1) * 32;
    const int bx = blockIdx.x, by = blockIdx.y;

    const int nt = K / BK;

    auto issue_stage = [&](int kt, int slot) {
        const float* Ag = A + (size_t)(by * BM) * K + kt * BK;
#pragma unroll
        for (int r = 0; r < (BM * 4) / 256; r++) {
            int ch = tid + r * 256;
            int m = ch >> 2, ko = (ch & 3) << 2;
            uint32_t dst = smem_u32(&As[(slot * BM + m) * AP + ko]);
            const float* src = Ag + (size_t)m * K + ko;
            asm volatile("cp.async.cg.shared.global [%0], [%1], 16;"
                         :: "r"(dst), "l"(src) : "memory");
        }
        const float* Bg = B + (size_t)(kt * BK) * Nn + bx * 128;
#pragma unroll
        for (int r = 0; r < 2; r++) {
            int ch = tid + r * 256;
            int kr = ch >> 5, no = (ch & 31) << 2;
            uint32_t dst = smem_u32(&Bs[(slot * BK + kr) * BP + no]);
            const float* src = Bg + (size_t)kr * Nn + no;
            asm volatile("cp.async.cg.shared.global [%0], [%1], 16;"
                         :: "r"(dst), "l"(src) : "memory");
        }
        asm volatile("cp.async.commit_group;" ::: "memory");
    };

    float acc[MF][4][4];
#pragma unroll
    for (int mf = 0; mf < MF; mf++)
#pragma unroll
        for (int nf = 0; nf < 4; nf++)
#pragma unroll
            for (int i = 0; i < 4; i++) acc[mf][nf][i] = 0.f;

#pragma unroll
    for (int s = 0; s < STAGES - 1; s++) issue_stage(s, s);

    for (int kt = 0; kt < nt; kt++) {
        asm volatile("cp.async.wait_group %0;" :: "n"(STAGES - 2) : "memory");
        __syncthreads();
        if (kt + STAGES - 1 < nt)
            issue_stage(kt + STAGES - 1, (kt + STAGES - 1) % STAGES);
        else
            asm volatile("cp.async.commit_group;" ::: "memory");

        const int slot = kt % STAGES;
        const uint32_t* Asl = reinterpret_cast<const uint32_t*>(&As[slot * BM * AP]);
        const uint32_t* Bsl = reinterpret_cast<const uint32_t*>(&Bs[slot * BK * BP]);

#pragma unroll
        for (int ks = 0; ks < 2; ks++) {
            const int k0 = ks * 8;
            uint32_t af[MF][4], bf[4][2];
#pragma unroll
            for (int mf = 0; mf < MF; mf++) {
                const int mrow = wm + mf * 16 + g;
                af[mf][0] = Asl[(size_t)mrow * AP + k0 + c];
                af[mf][1] = Asl[(size_t)(mrow + 8) * AP + k0 + c];
                af[mf][2] = Asl[(size_t)mrow * AP + k0 + c + 4];
                af[mf][3] = Asl[(size_t)(mrow + 8) * AP + k0 + c + 4];
            }
#pragma unroll
            for (int nf = 0; nf < 4; nf++) {
                const int ncol = wn + nf * 8 + g;
                bf[nf][0] = Bsl[(size_t)(k0 + c) * BP + ncol];
                bf[nf][1] = Bsl[(size_t)(k0 + c + 4) * BP + ncol];
            }
#pragma unroll
            for (int mf = 0; mf < MF; mf++)
#pragma unroll
                for (int nf = 0; nf < 4; nf++)
                    mma_tf32(acc[mf][nf], af[mf], bf[nf]);
        }
    }

#pragma unroll
    for (int mf = 0; mf < MF; mf++) {
#pragma unroll
        for (int nf = 0; nf < 4; nf++) {
            int row = by * BM + wm + mf * 16 + g;
            int col = bx * 128 + wn + nf * 8 + 2 * c;
#pragma unroll
            for (int half = 0; half < 2; half++) {
                int r = row + half * 8;
                float v0 = acc[mf][nf][half * 2 + 0];
                float v1 = acc[mf][nf][half * 2 + 1];
                if (EPI == 1) {
                    v0 += bias[col]     + res[(size_t)r * Nn + col];
                    v1 += bias[col + 1] + res[(size_t)r * Nn + col + 1];
                }
                if (EPI == 2) {
                    v0 += res[(size_t)r * Nn + col];
                    v1 += res[(size_t)r * Nn + col + 1];
                }
                if (EPI == 3) {
                    v0 = 0.5f * v0 * (1.f + erff(v0 * 0.70710678f));
                    v1 = 0.5f * v1 * (1.f + erff(v1 * 0.70710678f));
                    v0 = rnd_tf32(v0);
                    v1 = rnd_tf32(v1);
                }
                float2 o = make_float2(v0, v1);
                *reinterpret_cast<float2*>(C + (size_t)r * Nn + col) = o;
            }
        }
    }
}

// ---------------------------------------------------------------------------
// Tensor-core attention with split-tf32 (near-fp32 accurate).
// Block = (head, 64-query tile), 128 threads = 4 warps x 16 queries.
// qsrc rows are [Q(1024)|K(1024)|V(1024)], stride 3072 (both cross & latent).
// CROSS=1: keys j<PFX come from kvctx rows [K|V] stride 2048; OFF=PFX.
// Per 32-key tile: S = Q@K^T via 3-term split mma; fragment-space online
// softmax; P staged via smem; O += P@V via 3-term split mma.
// Fragment layouts (validated by the GEMM): a0=A[g][c] a1=A[g+8][c]
// a2=A[g][c+4] a3=A[g+8][c+4]; b0=B[k=c][n=g] b1=B[c+4][g];
// c0=(g,2c) c1=(g,2c+1) c2=(g+8,2c) c3=(g+8,2c+1).
// ---------------------------------------------------------------------------
#define QP 68   // Qs pitch
#define KP 40   // KT pitch  (bank = 8c+g, conflict-free)
#define VP 72   // Vs pitch  (bank = 8c+g, conflict-free)
#define PP 40   // Ps pitch  (bank = 8g+c, conflict-free)
#define ATT_SMEM ((64*QP + 2*64*KP + 2*32*VP + 4*16*PP) * 4)

template <int CROSS>
__global__ __launch_bounds__(128) void attn_kernel(
    const float* __restrict__ qsrc, const float* __restrict__ kvctx,
    float* __restrict__ out)
{
    const int OFF = CROSS ? PFX : 0;
    const int hbase = blockIdx.y * DHEAD;
    const int qbase = blockIdx.x * 64;
    const int wid = threadIdx.x >> 5, lane = threadIdx.x & 31;
    const int g = lane >> 2, c = lane & 3;
    const int ibase = qbase + wid * 16;

    extern __shared__ __align__(16) float sm[];
    float* Qs   = sm;                    // [64][QP]
    float* KThi = Qs   + 64 * QP;        // [64][KP]  (K transposed [d][key])
    float* KTlo = KThi + 64 * KP;
    float* Vhi  = KTlo + 64 * KP;        // [32][VP]  ([key][d])
    float* Vlo  = Vhi  + 32 * VP;
    float* Ps   = Vlo  + 32 * VP;        // [4][16][PP]

    // Stage Q tile (scaled by 1/8)
    {
        int qr = threadIdx.x >> 1;
        int half = (threadIdx.x & 1) * 32;
        const float* qp = qsrc + (size_t)(qbase + qr) * 3072 + hbase + half;
        float* dst = Qs + qr * QP + half;
#pragma unroll
        for (int u = 0; u < 8; u++) {
            float4 v = *reinterpret_cast<const float4*>(qp + u * 4);
            dst[u * 4 + 0] = v.x * 0.125f;
            dst[u * 4 + 1] = v.y * 0.125f;
            dst[u * 4 + 2] = v.z * 0.125f;
            dst[u * 4 + 3] = v.w * 0.125f;
        }
    }
    __syncthreads();

    // Extract Q fragments (hi/lo split), K dim = 64 -> 8 k-steps
    uint32_t qhi[8][4], qlo[8][4];
#pragma unroll
    for (int ks = 0; ks < 8; ks++) {
        const int k0 = ks * 8;
        const int r0 = (wid * 16 + g) * QP, r1 = (wid * 16 + g + 8) * QP;
        float v;
        v = Qs[r0 + k0 + c];     qhi[ks][0] = f2tf(v); qlo[ks][0] = f2tf(v - __uint_as_float(qhi[ks][0]));
        v = Qs[r1 + k0 + c];     qhi[ks][1] = f2tf(v); qlo[ks][1] = f2tf(v - __uint_as_float(qhi[ks][1]));
        v = Qs[r0 + k0 + c + 4]; qhi[ks][2] = f2tf(v); qlo[ks][2] = f2tf(v - __uint_as_float(qhi[ks][2]));
        v = Qs[r1 + k0 + c + 4]; qhi[ks][3] = f2tf(v); qlo[ks][3] = f2tf(v - __uint_as_float(qhi[ks][3]));
    }

    float O[8][4];
#pragma unroll
    for (int nf = 0; nf < 8; nf++)
#pragma unroll
        for (int e = 0; e < 4; e++) O[nf][e] = 0.f;
    float mrow0 = -3.0e38f, mrow1 = -3.0e38f;
    float den0 = 0.f, den1 = 0.f;

    const int ntiles = (qbase + 64 + OFF) / 32;
    float* Pw = Ps + wid * 16 * PP;

    for (int t = 0; t < ntiles; t++) {
        const int jt = t * 32;
        __syncthreads();
        // Stage K (transposed, hi/lo) and V (hi/lo)
        {
            int key = threadIdx.x >> 2;
            int d0  = (threadIdx.x & 3) * 16;
            int j = jt + key;
            const float *kp, *vp;
            if (CROSS && j < PFX) {
                kp = kvctx + (size_t)j * 2048 + hbase;
                vp = kp + INNER;
            } else {
                int jj = CROSS ? j - PFX : j;
                if (jj > LAT - 1) jj = LAT - 1;   // clamp; masked in compute
                kp = qsrc + (size_t)jj * 3072 + INNER + hbase;
                vp = kp + INNER;
            }
#pragma unroll
            for (int u = 0; u < 4; u++) {
                float4 k4 = *reinterpret_cast<const float4*>(kp + d0 + u * 4);
                float4 v4 = *reinterpret_cast<const float4*>(vp + d0 + u * 4);
                const float ke[4] = {k4.x, k4.y, k4.z, k4.w};
                float4 vh, vl;
                float* vhp = &vh.x; float* vlp = &vl.x;
                const float ve[4] = {v4.x, v4.y, v4.z, v4.w};
#pragma unroll
                for (int e = 0; e < 4; e++) {
                    int d = d0 + u * 4 + e;
                    float khi = rnd_tf32(ke[e]);
                    KThi[d * KP + key] = khi;
                    KTlo[d * KP + key] = rnd_tf32(ke[e] - khi);
                    float vhi = rnd_tf32(ve[e]);
                    vhp[e] = vhi;
                    vlp[e] = rnd_tf32(ve[e] - vhi);
                }
                *reinterpret_cast<float4*>(Vhi + key * VP + d0 + u * 4) = vh;
                *reinterpret_cast<float4*>(Vlo + key * VP + d0 + u * 4) = vl;
            }
        }
        __syncthreads();

        if (jt > ibase + 15 + OFF) continue;   // fully masked for this warp

        // ---- S = Q @ K^T (split: hi*hi + lo*hi + hi*lo) ----
        float Sh[4][4], Sl[4][4];
#pragma unroll
        for (int nf = 0; nf < 4; nf++)
#pragma unroll
            for (int e = 0; e < 4; e++) { Sh[nf][e] = 0.f; Sl[nf][e] = 0.f; }
        const uint32_t* KThu = reinterpret_cast<const uint32_t*>(KThi);
        const uint32_t* KTlu = reinterpret_cast<const uint32_t*>(KTlo);
#pragma unroll
        for (int nf = 0; nf < 4; nf++) {
            const int nn = nf * 8 + g;
#pragma unroll
            for (int ks = 0; ks < 8; ks++) {
                const int k0 = ks * 8;
                uint32_t bh[2], bl[2];
                bh[0] = KThu[(k0 + c) * KP + nn];
                bh[1] = KThu[(k0 + c + 4) * KP + nn];
                bl[0] = KTlu[(k0 + c) * KP + nn];
                bl[1] = KTlu[(k0 + c + 4) * KP + nn];
                mma_tf32(Sh[nf], qhi[ks], bh);
                mma_tf32(Sl[nf], qlo[ks], bh);
                mma_tf32(Sl[nf], qhi[ks], bl);
            }
        }

        // ---- merge + causal mask ----
        float S[4][4];
        const bool needmask = (jt + 31 > ibase + OFF);
#pragma unroll
        for (int nf = 0; nf < 4; nf++)
#pragma unroll
            for (int e = 0; e < 4; e++) {
                float sv = Sh[nf][e] + Sl[nf][e];
                if (needmask) {
                    int row = ibase + g + ((e >= 2) ? 8 : 0);
                    int col = jt + nf * 8 + 2 * c + (e & 1);
                    if (col > row + OFF) sv = -3.0e38f;
                }
                S[nf][e] = sv;
            }

        // ---- fragment-space online softmax ----
        float mx0 = S[0][0], mx1 = S[0][2];
#pragma unroll
        for (int nf = 0; nf < 4; nf++) {
            mx0 = fmaxf(mx0, fmaxf(S[nf][0], S[nf][1]));
            mx1 = fmaxf(mx1, fmaxf(S[nf][2], S[nf][3]));
        }
        mx0 = fmaxf(mx0, __shfl_xor_sync(0xffffffffu, mx0, 1));
        mx0 = fmaxf(mx0, __shfl_xor_sync(0xffffffffu, mx0, 2));
        mx1 = fmaxf(mx1, __shfl_xor_sync(0xffffffffu, mx1, 1));
        mx1 = fmaxf(mx1, __shfl_xor_sync(0xffffffffu, mx1, 2));
        float mn0 = fmaxf(mrow0, mx0);
        float mn1 = fmaxf(mrow1, mx1);
        float cc0 = __expf(mrow0 - mn0);
        float cc1 = __expf(mrow1 - mn1);
        mrow0 = mn0; mrow1 = mn1;

        float P[4][4];
        float ps0 = 0.f, ps1 = 0.f;
#pragma unroll
        for (int nf = 0; nf < 4; nf++) {
            P[nf][0] = __expf(S[nf][0] - mn0);
            P[nf][1] = __expf(S[nf][1] - mn0);
            P[nf][2] = __expf(S[nf][2] - mn1);
            P[nf][3] = __expf(S[nf][3] - mn1);
            ps0 += P[nf][0] + P[nf][1];
            ps1 += P[nf][2] + P[nf][3];
        }
        den0 = den0 * cc0 + ps0;
        den1 = den1 * cc1 + ps1;
#pragma unroll
        for (int nf = 0; nf < 8; nf++) {
            O[nf][0] *= cc0; O[nf][1] *= cc0;
            O[nf][2] *= cc1; O[nf][3] *= cc1;
        }

        // ---- stage P to smem ----
#pragma unroll
        for (int nf = 0; nf < 4; nf++) {
            *reinterpret_cast<float2*>(Pw + g * PP + nf * 8 + 2 * c) =
                make_float2(P[nf][0], P[nf][1]);
            *reinterpret_cast<float2*>(Pw + (g + 8) * PP + nf * 8 + 2 * c) =
                make_float2(P[nf][2], P[nf][3]);
        }
        __syncwarp();

        // ---- O += P @ V (split: Phi*Vhi + Plo*Vhi + Phi*Vlo) ----
        const uint32_t* Vhu = reinterpret_cast<const uint32_t*>(Vhi);
        const uint32_t* Vlu = reinterpret_cast<const uint32_t*>(Vlo);
#pragma unroll
        for (int ks2 = 0; ks2 < 4; ks2++) {
            const int k0 = ks2 * 8;
            uint32_t ahi[4], alo[4];
            float pv;
            pv = Pw[g * PP + k0 + c];           ahi[0] = f2tf(pv); alo[0] = f2tf(pv - __uint_as_float(ahi[0]));
            pv = Pw[(g + 8) * PP + k0 + c];     ahi[1] = f2tf(pv); alo[1] = f2tf(pv - __uint_as_float(ahi[1]));
            pv = Pw[g * PP + k0 + c + 4];       ahi[2] = f2tf(pv); alo[2] = f2tf(pv - __uint_as_float(ahi[2]));
            pv = Pw[(g + 8) * PP + k0 + c + 4]; ahi[3] = f2tf(pv); alo[3] = f2tf(pv - __uint_as_float(ahi[3]));
#pragma unroll
            for (int nf = 0; nf < 8; nf++) {
                const int nn = nf * 8 + g;
                uint32_t bh[2], bl[2];
                bh[0] = Vhu[(k0 + c) * VP + nn];
                bh[1] = Vhu[(k0 + c + 4) * VP + nn];
                bl[0] = Vlu[(k0 + c) * VP + nn];
                bl[1] = Vlu[(k0 + c + 4) * VP + nn];
                mma_tf32(O[nf], ahi, bh);
                mma_tf32(O[nf], alo, bh);
                mma_tf32(O[nf], ahi, bl);
            }
        }
        __syncwarp();
    }

    // ---- finalize: reduce den across the quad, normalize, write ----
    den0 += __shfl_xor_sync(0xffffffffu, den0, 1);
    den0 += __shfl_xor_sync(0xffffffffu, den0, 2);
    den1 += __shfl_xor_sync(0xffffffffu, den1, 1);
    den1 += __shfl_xor_sync(0xffffffffu, den1, 2);
    float r0 = 1.f / den0, r1 = 1.f / den1;
#pragma unroll
    for (int nf = 0; nf < 8; nf++) {
        int col = hbase + nf * 8 + 2 * c;
        float2 o0 = make_float2(rnd_tf32(O[nf][0] * r0), rnd_tf32(O[nf][1] * r0));
        float2 o1 = make_float2(rnd_tf32(O[nf][2] * r1), rnd_tf32(O[nf][3] * r1));
        *reinterpret_cast<float2*>(out + (size_t)(ibase + g) * INNER + col)     = o0;
        *reinterpret_cast<float2*>(out + (size_t)(ibase + g + 8) * INNER + col) = o1;
    }
}

// ---------------------------------------------------------------------------
// Host orchestration
// ---------------------------------------------------------------------------
static const int SMEM128 = (STAGES * (128 * 20 + BK * 136)) * 4;
static const int SMEM64  = (STAGES * ( 64 * 20 + BK * 136)) * 4;

static void run_sgemm(int epi, const float* A, const float* B, float* C,
                      const float* bias, const float* res, int M, int Nn, int K)
{
    int g128 = (Nn / 128) * (M / 128);
    if (g128 <= 64) {
        dim3 grid(Nn / 128, M / 64);
        switch (epi) {
            case 0: sgemm_kernel<64,0><<<grid, 256, SMEM64>>>(A, B, C, bias, res, M, Nn, K); break;
            case 1: sgemm_kernel<64,1><<<grid, 256, SMEM64>>>(A, B, C, bias, res, M, Nn, K); break;
            case 2: sgemm_kernel<64,2><<<grid, 256, SMEM64>>>(A, B, C, bias, res, M, Nn, K); break;
            case 3: sgemm_kernel<64,3><<<grid, 256, SMEM64>>>(A, B, C, bias, res, M, Nn, K); break;
        }
    } else {
        dim3 grid(Nn / 128, M / 128);
        switch (epi) {
            case 0: sgemm_kernel<128,0><<<grid, 256, SMEM128>>>(A, B, C, bias, res, M, Nn, K); break;
            case 1: sgemm_kernel<128,1><<<grid, 256, SMEM128>>>(A, B, C, bias, res, M, Nn, K); break;
            case 2: sgemm_kernel<128,2><<<grid, 256, SMEM128>>>(A, B, C, bias, res, M, Nn, K); break;
            case 3: sgemm_kernel<128,3><<<grid, 256, SMEM128>>>(A, B, C, bias, res, M, Nn, K); break;
        }
    }
}

static void run_round(const float* src, float* dst, size_t n)
{
    int n4 = (int)(n / 4);
    round_kernel<<<(n4 + 255) / 256, 256>>>(src, dst, n4);
}

extern "C" void kernel_launch(void* const* d_in, const int* in_sizes, int n_in,
                              void* d_out, int out_size)
{
    (void)in_sizes; (void)n_in; (void)out_size;

    const int*   x        = (const int*)  d_in[0];
    const float* tok_emb  = (const float*)d_in[1];
    const float* pos_emb  = (const float*)d_in[2];
    const float* ca_ln_g  = (const float*)d_in[3];
    const float* ca_ln_b  = (const float*)d_in[4];
    const float* ca_wq    = (const float*)d_in[5];
    const float* ca_wkv   = (const float*)d_in[6];
    const float* ca_wo    = (const float*)d_in[7];
    const float* ca_bo    = (const float*)d_in[8];
    const float* cf_ln_g  = (const float*)d_in[9];
    const float* cf_ln_b  = (const float*)d_in[10];
    const float* cf_w1    = (const float*)d_in[11];
    const float* cf_w2    = (const float*)d_in[12];
    const float* la_ln_g  = (const float*)d_in[13];
    const float* la_ln_b  = (const float*)d_in[14];
    const float* la_wqkv  = (const float*)d_in[15];
    const float* la_wo    = (const float*)d_in[16];
    const float* lf_ln_g  = (const float*)d_in[17];
    const float* lf_ln_b  = (const float*)d_in[18];
    const float* lf_w1    = (const float*)d_in[19];
    const float* lf_w2    = (const float*)d_in[20];
    const float* w_logits = (const float*)d_in[21];
    float* out = (float*)d_out;

    cudaFuncSetAttribute(sgemm_kernel<128,0>, cudaFuncAttributeMaxDynamicSharedMemorySize, SMEM128);
    cudaFuncSetAttribute(sgemm_kernel<128,1>, cudaFuncAttributeMaxDynamicSharedMemorySize, SMEM128);
    cudaFuncSetAttribute(sgemm_kernel<128,2>, cudaFuncAttributeMaxDynamicSharedMemorySize, SMEM128);
    cudaFuncSetAttribute(sgemm_kernel<128,3>, cudaFuncAttributeMaxDynamicSharedMemorySize, SMEM128);
    cudaFuncSetAttribute(attn_kernel<0>, cudaFuncAttributeMaxDynamicSharedMemorySize, ATT_SMEM);
    cudaFuncSetAttribute(attn_kernel<1>, cudaFuncAttributeMaxDynamicSharedMemorySize, ATT_SMEM);

    float *prefix, *h, *xn, *kvctx, *attn, *ff, *qkv, *w;
    cudaGetSymbolAddress((void**)&prefix, g_prefix);
    cudaGetSymbolAddress((void**)&h,      g_h);
    cudaGetSymbolAddress((void**)&xn,     g_xn);
    cudaGetSymbolAddress((void**)&kvctx,  g_kvctx);
    cudaGetSymbolAddress((void**)&attn,   g_attn);
    cudaGetSymbolAddress((void**)&ff,     g_ff);
    cudaGetSymbolAddress((void**)&qkv,    g_qkv);
    cudaGetSymbolAddress((void**)&w,      g_w);

    // 0. Pre-round / pack all weights to tf32 values
    {
        int n4 = (DMODEL * 3 * INNER) / 4;
        pack_cqkv_kernel<<<(n4 + 255) / 256, 256>>>(ca_wq, ca_wkv, w + W_CQKV);
    }
    run_round(ca_wkv,   w + W_WKV,  (size_t)DMODEL * 2 * INNER);
    run_round(ca_wo,    w + W_WO,   (size_t)INNER * DMODEL);
    run_round(cf_w1,    w + W_CF1,  (size_t)DMODEL * FFDIM);
    run_round(cf_w2,    w + W_CF2,  (size_t)FFDIM * DMODEL);
    run_round(la_wqkv,  w + W_LQKV, (size_t)DEPTH * DMODEL * 3 * INNER);
    run_round(la_wo,    w + W_LWO,  (size_t)DEPTH * INNER * DMODEL);
    run_round(lf_w1,    w + W_LF1,  (size_t)DEPTH * DMODEL * FFDIM);
    run_round(lf_w2,    w + W_LF2,  (size_t)DEPTH * FFDIM * DMODEL);
    run_round(w_logits, w + W_LOG,  (size_t)DMODEL * VOCAB);

    // 1. Embedding
    embed_kernel<<<(NCTX * DMODEL) / 256, 256>>>(x, tok_emb, pos_emb);

    // 2. Cross-attention block (fused qkv projection)
    ln_kernel<<<LAT, 256>>>(h, xn, ca_ln_g, ca_ln_b);
    run_sgemm(0, xn,     w + W_CQKV, qkv,   nullptr, nullptr, LAT, 3 * INNER, DMODEL);
    run_sgemm(0, prefix, w + W_WKV,  kvctx, nullptr, nullptr, PFX, 2 * INNER, DMODEL);
    {
        dim3 gg(LAT / 64, NHEAD);
        attn_kernel<1><<<gg, 128, ATT_SMEM>>>(qkv, kvctx, attn);
    }
    run_sgemm(1, attn, w + W_WO, h, ca_bo, h, LAT, DMODEL, INNER);

    // 3. Cross FFN
    ln_kernel<<<LAT, 256>>>(h, xn, cf_ln_g, cf_ln_b);
    run_sgemm(3, xn, w + W_CF1, ff, nullptr, nullptr, LAT, FFDIM, DMODEL);
    run_sgemm(2, ff, w + W_CF2, h, nullptr, h, LAT, DMODEL, FFDIM);

    // 4. Latent self-attention layers
    for (int l = 0; l < DEPTH; l++) {
        ln_kernel<<<LAT, 256>>>(h, xn, la_ln_g + (size_t)l * DMODEL, la_ln_b + (size_t)l * DMODEL);
        run_sgemm(0, xn, w + W_LQKV + (size_t)l * DMODEL * 3 * INNER, qkv,
                  nullptr, nullptr, LAT, 3 * INNER, DMODEL);
        {
            dim3 gg(LAT / 64, NHEAD);
            attn_kernel<0><<<gg, 128, ATT_SMEM>>>(qkv, nullptr, attn);
        }
        run_sgemm(2, attn, w + W_LWO + (size_t)l * INNER * DMODEL, h, nullptr, h, LAT, DMODEL, INNER);

        ln_kernel<<<LAT, 256>>>(h, xn, lf_ln_g + (size_t)l * DMODEL, lf_ln_b + (size_t)l * DMODEL);
        run_sgemm(3, xn, w + W_LF1 + (size_t)l * DMODEL * FFDIM, ff, nullptr, nullptr, LAT, FFDIM, DMODEL);
        run_sgemm(2, ff, w + W_LF2 + (size_t)l * FFDIM * DMODEL, h, nullptr, h, LAT, DMODEL, FFDIM);
    }

    // 5. Logits (round h into xn first: h itself must stay fp32)
    run_round(h, xn, (size_t)LAT * DMODEL);
    run_sgemm(0, xn, w + W_LOG, out, nullptr, nullptr, LAT, VOCAB, DMODEL);
}

// round 14
// speedup vs baseline: 1.5341x; 1.0717x over previous
#include <cuda_runtime.h>
#include <cuda_bf16.h>
#include <math.h>
#include <stdint.h>

// Problem constants
#define NCTX   4096
#define DMODEL 1024
#define NHEAD  16
#define DHEAD  64
#define DEPTH  4
#define PFX    3072
#define LAT    1024          // NCTX - PFX
#define FFDIM  4096
#define VOCAB  32000
#define INNER  1024          // NHEAD * DHEAD

// ---------------------------------------------------------------------------
// Scratch (static __device__ globals; no runtime allocation)
// ---------------------------------------------------------------------------
__device__ float g_prefix[PFX * DMODEL];
__device__ float g_h     [LAT * DMODEL];
__device__ float g_xn    [LAT * DMODEL];
__device__ float g_kvctx [PFX * 2 * INNER];
__device__ float g_attn  [LAT * INNER];
__device__ float g_ff    [LAT * FFDIM];
__device__ float g_qkv   [LAT * 3 * INNER];

// tf32-rounded weight scratch (one big buffer, float offsets)
#define W_CQKV  0
#define W_WKV   (W_CQKV + DMODEL * 3 * INNER)
#define W_WO    (W_WKV  + DMODEL * 2 * INNER)
#define W_CF1   (W_WO   + INNER * DMODEL)
#define W_CF2   (W_CF1  + DMODEL * FFDIM)
#define W_LQKV  (W_CF2  + FFDIM * DMODEL)
#define W_LWO   (W_LQKV + DEPTH * DMODEL * 3 * INNER)
#define W_LF1   (W_LWO  + DEPTH * INNER * DMODEL)
#define W_LF2   (W_LF1  + DEPTH * DMODEL * FFDIM)
#define W_LOG   (W_LF2  + DEPTH * FFDIM * DMODEL)
#define W_TOTAL (W_LOG  + DMODEL * VOCAB)
__device__ float g_w[W_TOTAL];

// ---------------------------------------------------------------------------
// tf32 rounding helpers
// ---------------------------------------------------------------------------
__device__ __forceinline__ uint32_t f2tf(float x) {
    uint32_t r;
    asm("cvt.rna.tf32.f32 %0, %1;" : "=r"(r) : "f"(x));
    return r;
}
__device__ __forceinline__ float rnd_tf32(float x) {
    return __uint_as_float(f2tf(x));
}

// ---------------------------------------------------------------------------
// Elementwise tf32 rounding pass. 4 independent float4 per thread (MLP=4).
// Caller guarantees n4 % 1024 == 0 (all our sizes are), grid = n4/1024.
// ---------------------------------------------------------------------------
__global__ void round_kernel(const float* __restrict__ in,
                             float* __restrict__ out, int n4)
{
    int i0 = blockIdx.x * 1024 + threadIdx.x;
    float4 v[4];
#pragma unroll
    for (int u = 0; u < 4; u++)
        v[u] = reinterpret_cast<const float4*>(in)[i0 + u * 256];
#pragma unroll
    for (int u = 0; u < 4; u++) {
        v[u].x = rnd_tf32(v[u].x); v[u].y = rnd_tf32(v[u].y);
        v[u].z = rnd_tf32(v[u].z); v[u].w = rnd_tf32(v[u].w);
        reinterpret_cast<float4*>(out)[i0 + u * 256] = v[u];
    }
}

// Pack [wq | wkv] -> row-major [DMODEL][3*INNER], tf32-rounded.
__global__ void pack_cqkv_kernel(const float* __restrict__ wq,
                                 const float* __restrict__ wkv,
                                 float* __restrict__ dst)
{
    int i = blockIdx.x * blockDim.x + threadIdx.x;  // over D*3I/4
    if (i >= (DMODEL * 3 * INNER) / 4) return;
    int i4 = i * 4;
    int d = i4 / (3 * INNER);
    int j = i4 % (3 * INNER);
    float4 v;
    if (j < INNER)
        v = *reinterpret_cast<const float4*>(wq + (size_t)d * INNER + j);
    else
        v = *reinterpret_cast<const float4*>(wkv + (size_t)d * 2 * INNER + (j - INNER));
    v.x = rnd_tf32(v.x); v.y = rnd_tf32(v.y);
    v.z = rnd_tf32(v.z); v.w = rnd_tf32(v.w);
    reinterpret_cast<float4*>(dst)[i] = v;
}

// ---------------------------------------------------------------------------
// Embedding (prefix feeds GEMM only -> pre-rounded; h stays fp32)
// ---------------------------------------------------------------------------
__global__ void embed_kernel(const int* __restrict__ x,
                             const float* __restrict__ tok,
                             const float* __restrict__ pos)
{
    int idx = blockIdx.x * blockDim.x + threadIdx.x;
    int n = idx >> 10;
    int d = idx & 1023;
    float v = tok[(size_t)x[n] * DMODEL + d] + pos[idx];
    if (n < PFX) g_prefix[(size_t)n * DMODEL + d] = rnd_tf32(v);
    else         g_h[(size_t)(n - PFX) * DMODEL + d] = v;
}

// ---------------------------------------------------------------------------
// LayerNorm (D=1024); output feeds GEMM A only -> pre-rounded to tf32
// ---------------------------------------------------------------------------
__global__ __launch_bounds__(256) void ln_kernel(
    const float* __restrict__ in, float* __restrict__ out,
    const float* __restrict__ g, const float* __restrict__ b)
{
    int row = blockIdx.x;
    const float* p = in + (size_t)row * DMODEL;
    float vals[4];
    float s = 0.f, s2 = 0.f;
#pragma unroll
    for (int u = 0; u < 4; u++) {
        float v = p[threadIdx.x + u * 256];
        vals[u] = v; s += v; s2 += v * v;
    }
#pragma unroll
    for (int o = 16; o; o >>= 1) {
        s  += __shfl_xor_sync(0xffffffffu, s,  o);
        s2 += __shfl_xor_sync(0xffffffffu, s2, o);
    }
    __shared__ float sh[2][8];
    int wid = threadIdx.x >> 5, lane = threadIdx.x & 31;
    if (lane == 0) { sh[0][wid] = s; sh[1][wid] = s2; }
    __syncthreads();
    s = 0.f; s2 = 0.f;
#pragma unroll
    for (int w = 0; w < 8; w++) { s += sh[0][w]; s2 += sh[1][w]; }
    float mean = s * (1.f / DMODEL);
    float var  = s2 * (1.f / DMODEL) - mean * mean;
    float inv  = rsqrtf(var + 1e-5f);
#pragma unroll
    for (int u = 0; u < 4; u++) {
        int d = threadIdx.x + u * 256;
        out[(size_t)row * DMODEL + d] =
            rnd_tf32((vals[u] - mean) * inv * g[d] + b[d]);
    }
}

// ---------------------------------------------------------------------------
// TF32 tensor-core GEMM with cp.async 3-stage pipeline, BK=32.
// Inputs MUST already be tf32-rounded.
// C[M,N] = A[M,K] @ B[K,N], row-major. mma.sync.m16n8k8 tf32, fp32 acc.
// Block tile BMx128, 256 threads = 8 warps (2M x 4N).
// Smem: A [m][k] pitch 36 (frag bank = 4g+c, conflict-free),
//       B [k][n] pitch 136 (frag bank = 8c+g, conflict-free).
// One __syncthreads per 32-deep k-tile; cp.async.cg 16B; wait_group<1>.
// Epilogues: 0 none | 1 +bias[col]+res | 2 +res | 3 exact GELU (tf32-rounded)
// ---------------------------------------------------------------------------
#define BK 32
#define STAGES 3

__device__ __forceinline__ uint32_t smem_u32(const void* p) {
    return static_cast<uint32_t>(__cvta_generic_to_shared(p));
}

__device__ __forceinline__ void mma_tf32(float* d, const uint32_t* a, const uint32_t* b) {
    asm volatile(
        "mma.sync.aligned.m16n8k8.row.col.f32.tf32.tf32.f32 "
        "{%0,%1,%2,%3}, {%4,%5,%6,%7}, {%8,%9}, {%0,%1,%2,%3};"
        : "+f"(d[0]), "+f"(d[1]), "+f"(d[2]), "+f"(d[3])
        : "r"(a[0]), "r"(a[1]), "r"(a[2]), "r"(a[3]), "r"(b[0]), "r"(b[1]));
}

template <int BM, int EPI>
__global__ __launch_bounds__(256, 2) void sgemm_kernel(
    const float* __restrict__ A, const float* __restrict__ B,
    float* __restrict__ C, const float* __restrict__ bias,
    const float* __restrict__ res, int M, int Nn, int K)
{
    constexpr int MF = BM / 32;
    constexpr int AP = BK + 4;    // 36
    constexpr int BP = 136;
    extern __shared__ __align__(16) float smem[];
    float* As = smem;                          // [STAGES][BM][AP]
    float* Bs = smem + STAGES * BM * AP;       // [STAGES][BK][BP]

    const int tid  = threadIdx.x;
    const int lane = tid & 31, wid = tid >> 5;
    const int g = lane >> 2, c = lane & 3;
    const int wm = (wid & 1) * (BM / 2);
    const int wn = (wid >> 1) * 32;
    const int bx = blockIdx.x, by = blockIdx.y;

    const int nt = K / BK;

    auto issue_stage = [&](int kt, int slot) {
        const float* Ag = A + (size_t)(by * BM) * K + kt * BK;
#pragma unroll
        for (int r = 0; r < BM / 32; r++) {          // BM*8/256 chunks/thread
            int ch = tid + r * 256;
            int m = ch >> 3, ko = (ch & 7) << 2;
            uint32_t dst = smem_u32(&As[(slot * BM + m) * AP + ko]);
            const float* src = Ag + (size_t)m * K + ko;
            asm volatile("cp.async.cg.shared.global [%0], [%1], 16;"
                         :: "r"(dst), "l"(src) : "memory");
        }
        const float* Bg = B + (size_t)(kt * BK) * Nn + bx * 128;
#pragma unroll
        for (int r = 0; r < 4; r++) {                // 32*32/256 chunks/thread
            int ch = tid + r * 256;
            int kr = ch >> 5, no = (ch & 31) << 2;
            uint32_t dst = smem_u32(&Bs[(slot * BK + kr) * BP + no]);
            const float* src = Bg + (size_t)kr * Nn + no;
            asm volatile("cp.async.cg.shared.global [%0], [%1], 16;"
                         :: "r"(dst), "l"(src) : "memory");
        }
        asm volatile("cp.async.commit_group;" ::: "memory");
    };

    float acc[MF][4][4];
#pragma unroll
    for (int mf = 0; mf < MF; mf++)
#pragma unroll
        for (int nf = 0; nf < 4; nf++)
#pragma unroll
            for (int i = 0; i < 4; i++) acc[mf][nf][i] = 0.f;

#pragma unroll
    for (int s = 0; s < STAGES - 1; s++) issue_stage(s, s);

    for (int kt = 0; kt < nt; kt++) {
        asm volatile("cp.async.wait_group %0;" :: "n"(STAGES - 2) : "memory");
        __syncthreads();
        if (kt + STAGES - 1 < nt)
            issue_stage(kt + STAGES - 1, (kt + STAGES - 1) % STAGES);
        else
            asm volatile("cp.async.commit_group;" ::: "memory");

        const int slot = kt % STAGES;
        const uint32_t* Asl = reinterpret_cast<const uint32_t*>(&As[slot * BM * AP]);
        const uint32_t* Bsl = reinterpret_cast<const uint32_t*>(&Bs[slot * BK * BP]);

#pragma unroll
        for (int ks = 0; ks < 4; ks++) {
            const int k0 = ks * 8;
            uint32_t af[MF][4], bf[4][2];
#pragma unroll
            for (int mf = 0; mf < MF; mf++) {
                const int mrow = wm + mf * 16 + g;
                af[mf][0] = Asl[(size_t)mrow * AP + k0 + c];
                af[mf][1] = Asl[(size_t)(mrow + 8) * AP + k0 + c];
                af[mf][2] = Asl[(size_t)mrow * AP + k0 + c + 4];
                af[mf][3] = Asl[(size_t)(mrow + 8) * AP + k0 + c + 4];
            }
#pragma unroll
            for (int nf = 0; nf < 4; nf++) {
                const int ncol = wn + nf * 8 + g;
                bf[nf][0] = Bsl[(size_t)(k0 + c) * BP + ncol];
                bf[nf][1] = Bsl[(size_t)(k0 + c + 4) * BP + ncol];
            }
#pragma unroll
            for (int mf = 0; mf < MF; mf++)
#pragma unroll
                for (int nf = 0; nf < 4; nf++)
                    mma_tf32(acc[mf][nf], af[mf], bf[nf]);
        }
    }

#pragma unroll
    for (int mf = 0; mf < MF; mf++) {
#pragma unroll
        for (int nf = 0; nf < 4; nf++) {
            int row = by * BM + wm + mf * 16 + g;
            int col = bx * 128 + wn + nf * 8 + 2 * c;
#pragma unroll
            for (int half = 0; half < 2; half++) {
                int r = row + half * 8;
                float v0 = acc[mf][nf][half * 2 + 0];
                float v1 = acc[mf][nf][half * 2 + 1];
                if (EPI == 1) {
                    v0 += bias[col]     + res[(size_t)r * Nn + col];
                    v1 += bias[col + 1] + res[(size_t)r * Nn + col + 1];
                }
                if (EPI == 2) {
                    v0 += res[(size_t)r * Nn + col];
                    v1 += res[(size_t)r * Nn + col + 1];
                }
                if (EPI == 3) {
                    v0 = 0.5f * v0 * (1.f + erff(v0 * 0.70710678f));
                    v1 = 0.5f * v1 * (1.f + erff(v1 * 0.70710678f));
                    v0 = rnd_tf32(v0);
                    v1 = rnd_tf32(v1);
                }
                float2 o = make_float2(v0, v1);
                *reinterpret_cast<float2*>(C + (size_t)r * Nn + col) = o;
            }
        }
    }
}

// ---------------------------------------------------------------------------
// Tensor-core attention with split-tf32 (unchanged from passing R11).
// ---------------------------------------------------------------------------
#define QP 68
#define KP 40
#define VP 72
#define PP 40
#define ATT_SMEM ((64*QP + 2*64*KP + 2*32*VP + 4*16*PP) * 4)

template <int CROSS>
__global__ __launch_bounds__(128) void attn_kernel(
    const float* __restrict__ qsrc, const float* __restrict__ kvctx,
    float* __restrict__ out)
{
    const int OFF = CROSS ? PFX : 0;
    const int hbase = blockIdx.y * DHEAD;
    const int qbase = blockIdx.x * 64;
    const int wid = threadIdx.x >> 5, lane = threadIdx.x & 31;
    const int g = lane >> 2, c = lane & 3;
    const int ibase = qbase + wid * 16;

    extern __shared__ __align__(16) float sm[];
    float* Qs   = sm;
    float* KThi = Qs   + 64 * QP;
    float* KTlo = KThi + 64 * KP;
    float* Vhi  = KTlo + 64 * KP;
    float* Vlo  = Vhi  + 32 * VP;
    float* Ps   = Vlo  + 32 * VP;

    {
        int qr = threadIdx.x >> 1;
        int half = (threadIdx.x & 1) * 32;
        const float* qp = qsrc + (size_t)(qbase + qr) * 3072 + hbase + half;
        float* dst = Qs + qr * QP + half;
#pragma unroll
        for (int u = 0; u < 8; u++) {
            float4 v = *reinterpret_cast<const float4*>(qp + u * 4);
            dst[u * 4 + 0] = v.x * 0.125f;
            dst[u * 4 + 1] = v.y * 0.125f;
            dst[u * 4 + 2] = v.z * 0.125f;
            dst[u * 4 + 3] = v.w * 0.125f;
        }
    }
    __syncthreads();

    uint32_t qhi[8][4], qlo[8][4];
#pragma unroll
    for (int ks = 0; ks < 8; ks++) {
        const int k0 = ks * 8;
        const int r0 = (wid * 16 + g) * QP, r1 = (wid * 16 + g + 8) * QP;
        float v;
        v = Qs[r0 + k0 + c];     qhi[ks][0] = f2tf(v); qlo[ks][0] = f2tf(v - __uint_as_float(qhi[ks][0]));
        v = Qs[r1 + k0 + c];     qhi[ks][1] = f2tf(v); qlo[ks][1] = f2tf(v - __uint_as_float(qhi[ks][1]));
        v = Qs[r0 + k0 + c + 4]; qhi[ks][2] = f2tf(v); qlo[ks][2] = f2tf(v - __uint_as_float(qhi[ks][2]));
        v = Qs[r1 + k0 + c + 4]; qhi[ks][3] = f2tf(v); qlo[ks][3] = f2tf(v - __uint_as_float(qhi[ks][3]));
    }

    float O[8][4];
#pragma unroll
    for (int nf = 0; nf < 8; nf++)
#pragma unroll
        for (int e = 0; e < 4; e++) O[nf][e] = 0.f;
    float mrow0 = -3.0e38f, mrow1 = -3.0e38f;
    float den0 = 0.f, den1 = 0.f;

    const int ntiles = (qbase + 64 + OFF) / 32;
    float* Pw = Ps + wid * 16 * PP;

    for (int t = 0; t < ntiles; t++) {
        const int jt = t * 32;
        __syncthreads();
        {
            int key = threadIdx.x >> 2;
            int d0  = (threadIdx.x & 3) * 16;
            int j = jt + key;
            const float *kp, *vp;
            if (CROSS && j < PFX) {
                kp = kvctx + (size_t)j * 2048 + hbase;
                vp = kp + INNER;
            } else {
                int jj = CROSS ? j - PFX : j;
                if (jj > LAT - 1) jj = LAT - 1;
                kp = qsrc + (size_t)jj * 3072 + INNER + hbase;
                vp = kp + INNER;
            }
#pragma unroll
            for (int u = 0; u < 4; u++) {
                float4 k4 = *reinterpret_cast<const float4*>(kp + d0 + u * 4);
                float4 v4 = *reinterpret_cast<const float4*>(vp + d0 + u * 4);
                const float ke[4] = {k4.x, k4.y, k4.z, k4.w};
                float4 vh, vl;
                float* vhp = &vh.x; float* vlp = &vl.x;
                const float ve[4] = {v4.x, v4.y, v4.z, v4.w};
#pragma unroll
                for (int e = 0; e < 4; e++) {
                    int d = d0 + u * 4 + e;
                    float khi = rnd_tf32(ke[e]);
                    KThi[d * KP + key] = khi;
                    KTlo[d * KP + key] = rnd_tf32(ke[e] - khi);
                    float vhi = rnd_tf32(ve[e]);
                    vhp[e] = vhi;
                    vlp[e] = rnd_tf32(ve[e] - vhi);
                }
                *reinterpret_cast<float4*>(Vhi + key * VP + d0 + u * 4) = vh;
                *reinterpret_cast<float4*>(Vlo + key * VP + d0 + u * 4) = vl;
            }
        }
        __syncthreads();

        if (jt > ibase + 15 + OFF) continue;

        float Sh[4][4], Sl[4][4];
#pragma unroll
        for (int nf = 0; nf < 4; nf++)
#pragma unroll
            for (int e = 0; e < 4; e++) { Sh[nf][e] = 0.f; Sl[nf][e] = 0.f; }
        const uint32_t* KThu = reinterpret_cast<const uint32_t*>(KThi);
        const uint32_t* KTlu = reinterpret_cast<const uint32_t*>(KTlo);
#pragma unroll
        for (int nf = 0; nf < 4; nf++) {
            const int nn = nf * 8 + g;
#pragma unroll
            for (int ks = 0; ks < 8; ks++) {
                const int k0 = ks * 8;
                uint32_t bh[2], bl[2];
                bh[0] = KThu[(k0 + c) * KP + nn];
                bh[1] = KThu[(k0 + c + 4) * KP + nn];
                bl[0] = KTlu[(k0 + c) * KP + nn];
                bl[1] = KTlu[(k0 + c + 4) * KP + nn];
                mma_tf32(Sh[nf], qhi[ks], bh);
                mma_tf32(Sl[nf], qlo[ks], bh);
                mma_tf32(Sl[nf], qhi[ks], bl);
            }
        }

        float S[4][4];
        const bool needmask = (jt + 31 > ibase + OFF);
#pragma unroll
        for (int nf = 0; nf < 4; nf++)
#pragma unroll
            for (int e = 0; e < 4; e++) {
                float sv = Sh[nf][e] + Sl[nf][e];
                if (needmask) {
                    int row = ibase + g + ((e >= 2) ? 8 : 0);
                    int col = jt + nf * 8 + 2 * c + (e & 1);
                    if (col > row + OFF) sv = -3.0e38f;
                }
                S[nf][e] = sv;
            }

        float mx0 = S[0][0], mx1 = S[0][2];
#pragma unroll
        for (int nf = 0; nf < 4; nf++) {
            mx0 = fmaxf(mx0, fmaxf(S[nf][0], S[nf][1]));
            mx1 = fmaxf(mx1, fmaxf(S[nf][2], S[nf][3]));
        }
        mx0 = fmaxf(mx0, __shfl_xor_sync(0xffffffffu, mx0, 1));
        mx0 = fmaxf(mx0, __shfl_xor_sync(0xffffffffu, mx0, 2));
        mx1 = fmaxf(mx1, __shfl_xor_sync(0xffffffffu, mx1, 1));
        mx1 = fmaxf(mx1, __shfl_xor_sync(0xffffffffu, mx1, 2));
        float mn0 = fmaxf(mrow0, mx0);
        float mn1 = fmaxf(mrow1, mx1);
        float cc0 = __expf(mrow0 - mn0);
        float cc1 = __expf(mrow1 - mn1);
        mrow0 = mn0; mrow1 = mn1;

        float P[4][4];
        float ps0 = 0.f, ps1 = 0.f;
#pragma unroll
        for (int nf = 0; nf < 4; nf++) {
            P[nf][0] = __expf(S[nf][0] - mn0);
            P[nf][1] = __expf(S[nf][1] - mn0);
            P[nf][2] = __expf(S[nf][2] - mn1);
            P[nf][3] = __expf(S[nf][3] - mn1);
            ps0 += P[nf][0] + P[nf][1];
            ps1 += P[nf][2] + P[nf][3];
        }
        den0 = den0 * cc0 + ps0;
        den1 = den1 * cc1 + ps1;
#pragma unroll
        for (int nf = 0; nf < 8; nf++) {
            O[nf][0] *= cc0; O[nf][1] *= cc0;
            O[nf][2] *= cc1; O[nf][3] *= cc1;
        }

#pragma unroll
        for (int nf = 0; nf < 4; nf++) {
            *reinterpret_cast<float2*>(Pw + g * PP + nf * 8 + 2 * c) =
                make_float2(P[nf][0], P[nf][1]);
            *reinterpret_cast<float2*>(Pw + (g + 8) * PP + nf * 8 + 2 * c) =
                make_float2(P[nf][2], P[nf][3]);
        }
        __syncwarp();

        const uint32_t* Vhu = reinterpret_cast<const uint32_t*>(Vhi);
        const uint32_t* Vlu = reinterpret_cast<const uint32_t*>(Vlo);
#pragma unroll
        for (int ks2 = 0; ks2 < 4; ks2++) {
            const int k0 = ks2 * 8;
            uint32_t ahi[4], alo[4];
            float pv;
            pv = Pw[g * PP + k0 + c];           ahi[0] = f2tf(pv); alo[0] = f2tf(pv - __uint_as_float(ahi[0]));
            pv = Pw[(g + 8) * PP + k0 + c];     ahi[1] = f2tf(pv); alo[1] = f2tf(pv - __uint_as_float(ahi[1]));
            pv = Pw[g * PP + k0 + c + 4];       ahi[2] = f2tf(pv); alo[2] = f2tf(pv - __uint_as_float(ahi[2]));
            pv = Pw[(g + 8) * PP + k0 + c + 4]; ahi[3] = f2tf(pv); alo[3] = f2tf(pv - __uint_as_float(ahi[3]));
#pragma unroll
            for (int nf = 0; nf < 8; nf++) {
                const int nn = nf * 8 + g;
                uint32_t bh[2], bl[2];
                bh[0] = Vhu[(k0 + c) * VP + nn];
                bh[1] = Vhu[(k0 + c + 4) * VP + nn];
                bl[0] = Vlu[(k0 + c) * VP + nn];
                bl[1] = Vlu[(k0 + c + 4) * VP + nn];
                mma_tf32(O[nf], ahi, bh);
                mma_tf32(O[nf], alo, bh);
                mma_tf32(O[nf], ahi, bl);
            }
        }
        __syncwarp();
    }

    den0 += __shfl_xor_sync(0xffffffffu, den0, 1);
    den0 += __shfl_xor_sync(0xffffffffu, den0, 2);
    den1 += __shfl_xor_sync(0xffffffffu, den1, 1);
    den1 += __shfl_xor_sync(0xffffffffu, den1, 2);
    float r0 = 1.f / den0, r1 = 1.f / den1;
#pragma unroll
    for (int nf = 0; nf < 8; nf++) {
        int col = hbase + nf * 8 + 2 * c;
        float2 o0 = make_float2(rnd_tf32(O[nf][0] * r0), rnd_tf32(O[nf][1] * r0));
        float2 o1 = make_float2(rnd_tf32(O[nf][2] * r1), rnd_tf32(O[nf][3] * r1));
        *reinterpret_cast<float2*>(out + (size_t)(ibase + g) * INNER + col)     = o0;
        *reinterpret_cast<float2*>(out + (size_t)(ibase + g + 8) * INNER + col) = o1;
    }
}

// ---------------------------------------------------------------------------
// Host orchestration
// ---------------------------------------------------------------------------
static const int SMEM128 = (STAGES * (128 * 36 + BK * 136)) * 4; // 107520 B
static const int SMEM64  = (STAGES * ( 64 * 36 + BK * 136)) * 4; //  79872 B

static void run_sgemm(int epi, const float* A, const float* B, float* C,
                      const float* bias, const float* res, int M, int Nn, int K)
{
    int g128 = (Nn / 128) * (M / 128);
    if (g128 <= 64) {
        dim3 grid(Nn / 128, M / 64);
        switch (epi) {
            case 0: sgemm_kernel<64,0><<<grid, 256, SMEM64>>>(A, B, C, bias, res, M, Nn, K); break;
            case 1: sgemm_kernel<64,1><<<grid, 256, SMEM64>>>(A, B, C, bias, res, M, Nn, K); break;
            case 2: sgemm_kernel<64,2><<<grid, 256, SMEM64>>>(A, B, C, bias, res, M, Nn, K); break;
            case 3: sgemm_kernel<64,3><<<grid, 256, SMEM64>>>(A, B, C, bias, res, M, Nn, K); break;
        }
    } else {
        dim3 grid(Nn / 128, M / 128);
        switch (epi) {
            case 0: sgemm_kernel<128,0><<<grid, 256, SMEM128>>>(A, B, C, bias, res, M, Nn, K); break;
            case 1: sgemm_kernel<128,1><<<grid, 256, SMEM128>>>(A, B, C, bias, res, M, Nn, K); break;
            case 2: sgemm_kernel<128,2><<<grid, 256, SMEM128>>>(A, B, C, bias, res, M, Nn, K); break;
            case 3: sgemm_kernel<128,3><<<grid, 256, SMEM128>>>(A, B, C, bias, res, M, Nn, K); break;
        }
    }
}

static void run_round(const float* src, float* dst, size_t n)
{
    int n4 = (int)(n / 4);                 // all call sites: n4 % 1024 == 0
    round_kernel<<<n4 / 1024, 256>>>(src, dst, n4);
}

extern "C" void kernel_launch(void* const* d_in, const int* in_sizes, int n_in,
                              void* d_out, int out_size)
{
    (void)in_sizes; (void)n_in; (void)out_size;

    const int*   x        = (const int*)  d_in[0];
    const float* tok_emb  = (const float*)d_in[1];
    const float* pos_emb  = (const float*)d_in[2];
    const float* ca_ln_g  = (const float*)d_in[3];
    const float* ca_ln_b  = (const float*)d_in[4];
    const float* ca_wq    = (const float*)d_in[5];
    const float* ca_wkv   = (const float*)d_in[6];
    const float* ca_wo    = (const float*)d_in[7];
    const float* ca_bo    = (const float*)d_in[8];
    const float* cf_ln_g  = (const float*)d_in[9];
    const float* cf_ln_b  = (const float*)d_in[10];
    const float* cf_w1    = (const float*)d_in[11];
    const float* cf_w2    = (const float*)d_in[12];
    const float* la_ln_g  = (const float*)d_in[13];
    const float* la_ln_b  = (const float*)d_in[14];
    const float* la_wqkv  = (const float*)d_in[15];
    const float* la_wo    = (const float*)d_in[16];
    const float* lf_ln_g  = (const float*)d_in[17];
    const float* lf_ln_b  = (const float*)d_in[18];
    const float* lf_w1    = (const float*)d_in[19];
    const float* lf_w2    = (const float*)d_in[20];
    const float* w_logits = (const float*)d_in[21];
    float* out = (float*)d_out;

    cudaFuncSetAttribute(sgemm_kernel<128,0>, cudaFuncAttributeMaxDynamicSharedMemorySize, SMEM128);
    cudaFuncSetAttribute(sgemm_kernel<128,1>, cudaFuncAttributeMaxDynamicSharedMemorySize, SMEM128);
    cudaFuncSetAttribute(sgemm_kernel<128,2>, cudaFuncAttributeMaxDynamicSharedMemorySize, SMEM128);
    cudaFuncSetAttribute(sgemm_kernel<128,3>, cudaFuncAttributeMaxDynamicSharedMemorySize, SMEM128);
    cudaFuncSetAttribute(sgemm_kernel<64,0>,  cudaFuncAttributeMaxDynamicSharedMemorySize, SMEM64);
    cudaFuncSetAttribute(sgemm_kernel<64,1>,  cudaFuncAttributeMaxDynamicSharedMemorySize, SMEM64);
    cudaFuncSetAttribute(sgemm_kernel<64,2>,  cudaFuncAttributeMaxDynamicSharedMemorySize, SMEM64);
    cudaFuncSetAttribute(sgemm_kernel<64,3>,  cudaFuncAttributeMaxDynamicSharedMemorySize, SMEM64);
    cudaFuncSetAttribute(attn_kernel<0>, cudaFuncAttributeMaxDynamicSharedMemorySize, ATT_SMEM);
    cudaFuncSetAttribute(attn_kernel<1>, cudaFuncAttributeMaxDynamicSharedMemorySize, ATT_SMEM);

    float *prefix, *h, *xn, *kvctx, *attn, *ff, *qkv, *w;
    cudaGetSymbolAddress((void**)&prefix, g_prefix);
    cudaGetSymbolAddress((void**)&h,      g_h);
    cudaGetSymbolAddress((void**)&xn,     g_xn);
    cudaGetSymbolAddress((void**)&kvctx,  g_kvctx);
    cudaGetSymbolAddress((void**)&attn,   g_attn);
    cudaGetSymbolAddress((void**)&ff,     g_ff);
    cudaGetSymbolAddress((void**)&qkv,    g_qkv);
    cudaGetSymbolAddress((void**)&w,      g_w);

    // 0. Pre-round / pack all weights to tf32 values
    {
        int n4 = (DMODEL * 3 * INNER) / 4;
        pack_cqkv_kernel<<<(n4 + 255) / 256, 256>>>(ca_wq, ca_wkv, w + W_CQKV);
    }
    run_round(ca_wkv,   w + W_WKV,  (size_t)DMODEL * 2 * INNER);
    run_round(ca_wo,    w + W_WO,   (size_t)INNER * DMODEL);
    run_round(cf_w1,    w + W_CF1,  (size_t)DMODEL * FFDIM);
    run_round(cf_w2,    w + W_CF2,  (size_t)FFDIM * DMODEL);
    run_round(la_wqkv,  w + W_LQKV, (size_t)DEPTH * DMODEL * 3 * INNER);
    run_round(la_wo,    w + W_LWO,  (size_t)DEPTH * INNER * DMODEL);
    run_round(lf_w1,    w + W_LF1,  (size_t)DEPTH * DMODEL * FFDIM);
    run_round(lf_w2,    w + W_LF2,  (size_t)DEPTH * FFDIM * DMODEL);
    run_round(w_logits, w + W_LOG,  (size_t)DMODEL * VOCAB);

    // 1. Embedding
    embed_kernel<<<(NCTX * DMODEL) / 256, 256>>>(x, tok_emb, pos_emb);

    // 2. Cross-attention block (fused qkv projection)
    ln_kernel<<<LAT, 256>>>(h, xn, ca_ln_g, ca_ln_b);
    run_sgemm(0, xn,     w + W_CQKV, qkv,   nullptr, nullptr, LAT, 3 * INNER, DMODEL);
    run_sgemm(0, prefix, w + W_WKV,  kvctx, nullptr, nullptr, PFX, 2 * INNER, DMODEL);
    {
        dim3 gg(LAT / 64, NHEAD);
        attn_kernel<1><<<gg, 128, ATT_SMEM>>>(qkv, kvctx, attn);
    }
    run_sgemm(1, attn, w + W_WO, h, ca_bo, h, LAT, DMODEL, INNER);

    // 3. Cross FFN
    ln_kernel<<<LAT, 256>>>(h, xn, cf_ln_g, cf_ln_b);
    run_sgemm(3, xn, w + W_CF1, ff, nullptr, nullptr, LAT, FFDIM, DMODEL);
    run_sgemm(2, ff, w + W_CF2, h, nullptr, h, LAT, DMODEL, FFDIM);

    // 4. Latent self-attention layers
    for (int l = 0; l < DEPTH; l++) {
        ln_kernel<<<LAT, 256>>>(h, xn, la_ln_g + (size_t)l * DMODEL, la_ln_b + (size_t)l * DMODEL);
        run_sgemm(0, xn, w + W_LQKV + (size_t)l * DMODEL * 3 * INNER, qkv,
                  nullptr, nullptr, LAT, 3 * INNER, DMODEL);
        {
            dim3 gg(LAT / 64, NHEAD);
            attn_kernel<0><<<gg, 128, ATT_SMEM>>>(qkv, nullptr, attn);
        }
        run_sgemm(2, attn, w + W_LWO + (size_t)l * INNER * DMODEL, h, nullptr, h, LAT, DMODEL, INNER);

        ln_kernel<<<LAT, 256>>>(h, xn, lf_ln_g + (size_t)l * DMODEL, lf_ln_b + (size_t)l * DMODEL);
        run_sgemm(3, xn, w + W_LF1 + (size_t)l * DMODEL * FFDIM, ff, nullptr, nullptr, LAT, FFDIM, DMODEL);
        run_sgemm(2, ff, w + W_LF2 + (size_t)l * FFDIM * DMODEL, h, nullptr, h, LAT, DMODEL, FFDIM);
    }

    // 5. Logits (round h into xn first: h itself must stay fp32)
    run_round(h, xn, (size_t)LAT * DMODEL);
    run_sgemm(0, xn, w + W_LOG, out, nullptr, nullptr, LAT, VOCAB, DMODEL);
}